// round 7
// baseline (speedup 1.0000x reference)
#include <cuda_runtime.h>
#include <cuda_fp16.h>
#include <cstdint>

#define D_MODEL 1024
#define N_HEADS 16
#define D_HEAD  64
#define BATCH   4
#define SEQ     1024
#define ROWS    (BATCH * SEQ)        // 4096
#define BH      (BATCH * N_HEADS)    // 64
#define QKVN    3072
#define GK      1024
#define EPS     1e-5f

// ---------------- scratch ----------------------------------------------------
__device__ __align__(16) __half g_xh  [ROWS * D_MODEL];
__device__ __align__(16) __half g_qkv [ROWS * QKVN];
__device__ __align__(16) __half g_vt  [BH * D_HEAD * SEQ];   // V transposed [bh][d][s]
__device__ __align__(16) __half g_Bqkv[QKVN * D_MODEL];
__device__ __align__(16) __half g_Bo  [D_MODEL * D_MODEL];
__device__ __align__(16) __half g_B1  [D_MODEL * D_MODEL];
__device__ __align__(16) __half g_B2  [D_MODEL * D_MODEL];
__device__ __align__(16) __half g_ctx [ROWS * D_MODEL];
__device__ __align__(16) __half g_y1h [ROWS * D_MODEL];
__device__ __align__(16) __half g_hh  [ROWS * D_MODEL];
__device__ __align__(16) float  g_bqkv[QKVN];
__device__ __align__(16) float  g_tmp [ROWS * D_MODEL];
__device__ __align__(16) float  g_y1  [ROWS * D_MODEL];

// ---------------- helpers ----------------------------------------------------
__device__ __forceinline__ uint32_t smem_u32(const void* p) {
    uint32_t a;
    asm("{ .reg .u64 t; cvta.to.shared.u64 t, %1; cvt.u32.u64 %0, t; }" : "=r"(a) : "l"(p));
    return a;
}
#define SWZ(o) ((o) ^ (((o) >> 3) & 0x70))

__device__ __forceinline__ void cp16(uint32_t dst, const void* src) {
    asm volatile("cp.async.cg.shared.global [%0], [%1], 16;" :: "r"(dst), "l"(src) : "memory");
}
__device__ __forceinline__ void cp_commit() {
    asm volatile("cp.async.commit_group;" ::: "memory");
}
__device__ __forceinline__ void cp_wait1() {
    asm volatile("cp.async.wait_group 1;" ::: "memory");
}

__device__ __forceinline__ void ldsm4(uint32_t& r0, uint32_t& r1, uint32_t& r2, uint32_t& r3,
                                      uint32_t a) {
    asm volatile("ldmatrix.sync.aligned.m8n8.x4.shared.b16 {%0,%1,%2,%3}, [%4];"
                 : "=r"(r0), "=r"(r1), "=r"(r2), "=r"(r3) : "r"(a));
}
__device__ __forceinline__ void mma_h(float* c, const uint32_t* a, uint32_t b0, uint32_t b1) {
    asm volatile(
        "mma.sync.aligned.m16n8k16.row.col.f32.f16.f16.f32 "
        "{%0,%1,%2,%3}, {%4,%5,%6,%7}, {%8,%9}, {%0,%1,%2,%3};"
        : "+f"(c[0]), "+f"(c[1]), "+f"(c[2]), "+f"(c[3])
        : "r"(a[0]), "r"(a[1]), "r"(a[2]), "r"(a[3]), "r"(b0), "r"(b1));
}

// ---------------- fp16 GEMM: C[m][n] = A[m][k] * Bt[n][k]^T + bias -----------
// tile 128 x BN x 64, 256 threads (8 warps: 4m x 2n), 3-stage cp.async.
// BN=128: 1 CTA/SM heavyweight; BN=64: 3 CTAs/SM lightweight.
template <int BN>
struct GCfg {
    static constexpr int STAGE = 16384 + BN * 128;   // A 16KB + B BN*64*2
    static constexpr int SMEM  = 3 * STAGE;
    static constexpr int NN    = BN / 32;            // per-warp 16-col subtiles
};

template <int BN, int RELU, int OUTHALF, int VT>
__global__ void __launch_bounds__(256, (BN == 64) ? 3 : 1) gemm_h(
    const __half* __restrict__ A, const __half* __restrict__ Bt,
    const float* __restrict__ bias, float* __restrict__ Cf,
    __half* __restrict__ Ch, __half* __restrict__ vt, int Nld)
{
    constexpr int NN = GCfg<BN>::NN;
    constexpr int STAGE = GCfg<BN>::STAGE;
    extern __shared__ char sm[];
    const uint32_t sb = smem_u32(sm);
    const int tid = threadIdx.x, wid = tid >> 5, lane = tid & 31;
    const int m0 = blockIdx.y * 128, n0 = blockIdx.x * BN;
    const int wM = (wid & 3) * 32, wN = (wid >> 2) * (BN / 2);

    float acc[2][2 * NN][4];
#pragma unroll
    for (int t = 0; t < 2; t++)
#pragma unroll
        for (int n = 0; n < 2 * NN; n++)
#pragma unroll
            for (int j = 0; j < 4; j++) acc[t][n][j] = 0.f;

    auto load_stage = [&](int s, int k0) {
        const uint32_t base = sb + (uint32_t)s * STAGE;
#pragma unroll
        for (int i = 0; i < 4; i++) {
            int c = tid + i * 256;
            int r = c >> 3, q = c & 7;
            cp16(base + SWZ((uint32_t)(r * 128 + q * 16)),
                 A + (size_t)(m0 + r) * GK + k0 + q * 8);
        }
#pragma unroll
        for (int i = 0; i < NN; i++) {
            int c = tid + i * 256;
            int r = c >> 3, q = c & 7;
            cp16(base + 16384u + SWZ((uint32_t)(r * 128 + q * 16)),
                 Bt + (size_t)(n0 + r) * GK + k0 + q * 8);
        }
    };

    load_stage(0, 0); cp_commit();
    load_stage(1, 64); cp_commit();
    cp_wait1();
    __syncthreads();

    const int lr15 = lane & 15, l16 = (lane & 16) ? 16 : 0;
    const int bR = (lane & 7) + ((lane & 16) ? 8 : 0), b16 = (lane & 8) ? 16 : 0;

    for (int it = 0; it < 16; it++) {
        if (it + 2 < 16) load_stage((it + 2) % 3, (it + 2) * 64);
        cp_commit();

        const uint32_t aB = sb + (uint32_t)(it % 3) * STAGE;
        const uint32_t bB = aB + 16384u;
#pragma unroll
        for (int kb = 0; kb < 4; kb++) {
            uint32_t a[2][4];
#pragma unroll
            for (int t = 0; t < 2; t++)
                ldsm4(a[t][0], a[t][1], a[t][2], a[t][3],
                      aB + SWZ((uint32_t)((wM + t * 16 + lr15) * 128 + kb * 32 + l16)));
#pragma unroll
            for (int nn = 0; nn < NN; nn++) {
                uint32_t b0, b1, b2, b3;
                ldsm4(b0, b1, b2, b3,
                      bB + SWZ((uint32_t)((wN + nn * 16 + bR) * 128 + kb * 32 + b16)));
#pragma unroll
                for (int t = 0; t < 2; t++) {
                    mma_h(acc[t][2 * nn],     a[t], b0, b1);
                    mma_h(acc[t][2 * nn + 1], a[t], b2, b3);
                }
            }
        }
        cp_wait1();
        __syncthreads();
    }

    const int tq = lane & 3, g = lane >> 2;
#pragma unroll
    for (int t = 0; t < 2; t++) {
        const int r0 = m0 + wM + t * 16 + g;
#pragma unroll
        for (int n = 0; n < 2 * NN; n++) {
            const int cc = n0 + wN + n * 8 + 2 * tq;
            const float2 bv = *(const float2*)(bias + cc);
            float v0 = acc[t][n][0] + bv.x;
            float v1 = acc[t][n][1] + bv.y;
            float v2 = acc[t][n][2] + bv.x;
            float v3 = acc[t][n][3] + bv.y;
            if (RELU) {
                v0 = fmaxf(v0, 0.f); v1 = fmaxf(v1, 0.f);
                v2 = fmaxf(v2, 0.f); v3 = fmaxf(v3, 0.f);
            }
            if (VT && n0 >= 2048) {
                const int b = r0 >> 10, s = r0 & 1023;
                const int rel = cc - 2048;
                const int h = rel >> 6, d = rel & 63;
                __half* vp = vt + ((size_t)(b * 16 + h) * 64 + d) * 1024 + s;
                vp[0]        = __float2half_rn(v0);
                vp[1024]     = __float2half_rn(v1);
                vp[8]        = __float2half_rn(v2);
                vp[1024 + 8] = __float2half_rn(v3);
            } else if (OUTHALF) {
                *(__half2*)(Ch + (size_t)r0 * Nld + cc)       = __floats2half2_rn(v0, v1);
                *(__half2*)(Ch + (size_t)(r0 + 8) * Nld + cc) = __floats2half2_rn(v2, v3);
            } else {
                *(float2*)(Cf + (size_t)r0 * Nld + cc)       = make_float2(v0, v1);
                *(float2*)(Cf + (size_t)(r0 + 8) * Nld + cc) = make_float2(v2, v3);
            }
        }
    }
}

// ---------------- tensor-core flash attention (128-row q-tile, 8 warps) ------
__global__ void __launch_bounds__(256) attn_mma(const __half* __restrict__ qkv,
                                               const __half* __restrict__ vt,
                                               __half* __restrict__ ctx)
{
    __shared__ __align__(16) __half Qs[128 * 64];
    __shared__ __align__(16) __half Ks[2][64 * 64];
    __shared__ __align__(16) __half Vts[2][64 * 64];

    const int bh = blockIdx.y, b = bh >> 4, h = bh & 15;
    const int s0 = blockIdx.x * 128;
    const int tid = threadIdx.x, wid = tid >> 5, lane = tid & 31;
    const uint32_t qB = smem_u32(Qs);
    const uint32_t kB0 = smem_u32(Ks), vB0 = smem_u32(Vts);

#pragma unroll
    for (int i = 0; i < 4; i++) {
        int c = tid + i * 256;
        int r = c >> 3, q = c & 7;
        cp16(qB + SWZ((uint32_t)(r * 128 + q * 16)),
             qkv + (size_t)(b * SEQ + s0 + r) * QKVN + h * 64 + q * 8);
    }
    auto load_kv = [&](int buf, int t) {
#pragma unroll
        for (int i = 0; i < 2; i++) {
            int c = tid + i * 256;
            int r = c >> 3, q = c & 7;
            cp16(kB0 + buf * 8192u + SWZ((uint32_t)(r * 128 + q * 16)),
                 qkv + (size_t)(b * SEQ + t * 64 + r) * QKVN + 1024 + h * 64 + q * 8);
            cp16(vB0 + buf * 8192u + SWZ((uint32_t)(r * 128 + q * 16)),
                 vt + ((size_t)bh * 64 + r) * SEQ + t * 64 + q * 8);
        }
    };
    load_kv(0, 0); cp_commit();
    load_kv(1, 1); cp_commit();
    cp_wait1();
    __syncthreads();

    const int lr15 = lane & 15, l16 = (lane & 16) ? 16 : 0;
    const int bR = (lane & 7) + ((lane & 16) ? 8 : 0), b16 = (lane & 8) ? 16 : 0;

    // Q fragments for this warp's 16-row strip, scaled by 1/8 (exact in fp16)
    uint32_t aq[4][4];
    const __half2 sc = __floats2half2_rn(0.125f, 0.125f);
#pragma unroll
    for (int kb = 0; kb < 4; kb++) {
        ldsm4(aq[kb][0], aq[kb][1], aq[kb][2], aq[kb][3],
              qB + SWZ((uint32_t)((wid * 16 + lr15) * 128 + kb * 32 + l16)));
#pragma unroll
        for (int j = 0; j < 4; j++) {
            __half2 v = *reinterpret_cast<__half2*>(&aq[kb][j]);
            v = __hmul2(v, sc);
            aq[kb][j] = *reinterpret_cast<uint32_t*>(&v);
        }
    }

    float o[8][4];
#pragma unroll
    for (int j = 0; j < 8; j++)
#pragma unroll
        for (int k = 0; k < 4; k++) o[j][k] = 0.f;
    float mr0 = -1e30f, mr1 = -1e30f, lp0 = 0.f, lp1 = 0.f;

    for (int t = 0; t < 16; t++) {
        const uint32_t kB = kB0 + (t & 1) * 8192u;
        const uint32_t vB = vB0 + (t & 1) * 8192u;

        // S = Q K^T
        float s[8][4];
#pragma unroll
        for (int j = 0; j < 8; j++)
#pragma unroll
            for (int k = 0; k < 4; k++) s[j][k] = 0.f;
#pragma unroll
        for (int kb = 0; kb < 4; kb++) {
#pragma unroll
            for (int nn = 0; nn < 4; nn++) {
                uint32_t b0, b1, b2, b3;
                ldsm4(b0, b1, b2, b3,
                      kB + SWZ((uint32_t)((nn * 16 + bR) * 128 + kb * 32 + b16)));
                mma_h(s[2 * nn],     aq[kb], b0, b1);
                mma_h(s[2 * nn + 1], aq[kb], b2, b3);
            }
        }

        // online softmax (rows g and g+8)
        float mt0 = s[0][0], mt1 = s[0][2];
#pragma unroll
        for (int j = 0; j < 8; j++) {
            mt0 = fmaxf(mt0, fmaxf(s[j][0], s[j][1]));
            mt1 = fmaxf(mt1, fmaxf(s[j][2], s[j][3]));
        }
#pragma unroll
        for (int off = 1; off <= 2; off <<= 1) {
            mt0 = fmaxf(mt0, __shfl_xor_sync(0xFFFFFFFF, mt0, off));
            mt1 = fmaxf(mt1, __shfl_xor_sync(0xFFFFFFFF, mt1, off));
        }
        const float nm0 = fmaxf(mr0, mt0), nm1 = fmaxf(mr1, mt1);
        const float al0 = __expf(mr0 - nm0), al1 = __expf(mr1 - nm1);
        mr0 = nm0; mr1 = nm1;
        float ps0 = 0.f, ps1 = 0.f;
#pragma unroll
        for (int j = 0; j < 8; j++) {
            s[j][0] = __expf(s[j][0] - nm0);
            s[j][1] = __expf(s[j][1] - nm0);
            s[j][2] = __expf(s[j][2] - nm1);
            s[j][3] = __expf(s[j][3] - nm1);
            ps0 += s[j][0] + s[j][1];
            ps1 += s[j][2] + s[j][3];
        }
        lp0 = lp0 * al0 + ps0;
        lp1 = lp1 * al1 + ps1;
#pragma unroll
        for (int j = 0; j < 8; j++) {
            o[j][0] *= al0; o[j][1] *= al0;
            o[j][2] *= al1; o[j][3] *= al1;
        }

        // O += P Vt
#pragma unroll
        for (int kb = 0; kb < 4; kb++) {
            uint32_t pa[4];
            __half2 p0 = __floats2half2_rn(s[2 * kb][0], s[2 * kb][1]);
            __half2 p1 = __floats2half2_rn(s[2 * kb][2], s[2 * kb][3]);
            __half2 p2 = __floats2half2_rn(s[2 * kb + 1][0], s[2 * kb + 1][1]);
            __half2 p3 = __floats2half2_rn(s[2 * kb + 1][2], s[2 * kb + 1][3]);
            pa[0] = *reinterpret_cast<uint32_t*>(&p0);
            pa[1] = *reinterpret_cast<uint32_t*>(&p1);
            pa[2] = *reinterpret_cast<uint32_t*>(&p2);
            pa[3] = *reinterpret_cast<uint32_t*>(&p3);
#pragma unroll
            for (int nn = 0; nn < 4; nn++) {
                uint32_t b0, b1, b2, b3;
                ldsm4(b0, b1, b2, b3,
                      vB + SWZ((uint32_t)((nn * 16 + bR) * 128 + kb * 32 + b16)));
                mma_h(o[2 * nn],     pa, b0, b1);
                mma_h(o[2 * nn + 1], pa, b2, b3);
            }
        }

        __syncthreads();
        if (t + 2 < 16) load_kv(t & 1, t + 2);
        cp_commit();
        cp_wait1();
        __syncthreads();
    }

#pragma unroll
    for (int off = 1; off <= 2; off <<= 1) {
        lp0 += __shfl_xor_sync(0xFFFFFFFF, lp0, off);
        lp1 += __shfl_xor_sync(0xFFFFFFFF, lp1, off);
    }
    const float i0 = 1.f / lp0, i1 = 1.f / lp1;
    const int g = lane >> 2, tq = lane & 3;
    const int r0 = b * SEQ + s0 + wid * 16 + g;
#pragma unroll
    for (int j = 0; j < 8; j++) {
        const int cc = h * 64 + 8 * j + 2 * tq;
        *(__half2*)(ctx + (size_t)r0 * D_MODEL + cc) =
            __floats2half2_rn(o[j][0] * i0, o[j][1] * i0);
        *(__half2*)(ctx + (size_t)(r0 + 8) * D_MODEL + cc) =
            __floats2half2_rn(o[j][2] * i1, o[j][3] * i1);
    }
}

// ---------------- fused prep (proven in R5) -----------------------------------
__global__ void prep_kernel(
    const float* __restrict__ x,
    const float* __restrict__ Wq, const float* __restrict__ Wk, const float* __restrict__ Wv,
    const float* __restrict__ Wo, const float* __restrict__ W1, const float* __restrict__ W2,
    const float* __restrict__ bq, const float* __restrict__ bk, const float* __restrict__ bv,
    __half* __restrict__ xh, __half* __restrict__ Bqkv,
    __half* __restrict__ Bo, __half* __restrict__ B1, __half* __restrict__ B2,
    float* __restrict__ bqkv)
{
    const int z = blockIdx.z;
    const int tx = threadIdx.x, ty = threadIdx.y;
    const int tid = ty * 32 + tx;

    if (z == 0) {
        const int c0 = blockIdx.x * 32, r0 = blockIdx.y * 32;
#pragma unroll
        for (int i = 0; i < 32; i += 8)
            xh[(size_t)(r0 + ty + i) * 1024 + c0 + tx] =
                __float2half_rn(x[(size_t)(r0 + ty + i) * 1024 + c0 + tx]);
        if (blockIdx.x == 0 && blockIdx.y == 0) {
            for (int i = tid; i < 3072; i += 256)
                bqkv[i] = (i < 1024) ? bq[i] : (i < 2048) ? bk[i - 1024] : bv[i - 2048];
        }
        return;
    }
    if (blockIdx.y >= 32) return;
    __shared__ float t[32][33];

    if (z <= 3) {
        const float* W = (z == 1) ? Wq : (z == 2) ? Wk : Wv;
        __half* out = Bqkv + (size_t)(z - 1) * 1024 * 1024;
        const int hh = blockIdx.x >> 1, d0 = (blockIdx.x & 1) * 32;
        const int k0 = blockIdx.y * 32;
#pragma unroll
        for (int i = 0; i < 32; i += 8)
            t[ty + i][tx] = W[((size_t)hh * 1024 + k0 + ty + i) * 64 + d0 + tx];
        __syncthreads();
#pragma unroll
        for (int i = 0; i < 32; i += 8)
            out[(size_t)(hh * 64 + d0 + ty + i) * 1024 + k0 + tx] =
                __float2half_rn(t[tx][ty + i]);
    } else {
        const float* W = (z == 4) ? Wo : (z == 5) ? W1 : W2;
        __half* out = (z == 4) ? Bo : (z == 5) ? B1 : B2;
        const int n0 = blockIdx.x * 32, k0 = blockIdx.y * 32;
#pragma unroll
        for (int i = 0; i < 32; i += 8)
            t[ty + i][tx] = W[(size_t)(k0 + ty + i) * 1024 + n0 + tx];
        __syncthreads();
#pragma unroll
        for (int i = 0; i < 32; i += 8)
            out[(size_t)(n0 + ty + i) * 1024 + k0 + tx] = __float2half_rn(t[tx][ty + i]);
    }
}

// ---------------- residual + LayerNorm ---------------------------------------
template <bool DUAL>
__global__ __launch_bounds__(256) void add_ln_kernel(
    const float* __restrict__ A, const float* __restrict__ Bb,
    const float* __restrict__ g, const float* __restrict__ be,
    float* __restrict__ out, __half* __restrict__ outh)
{
    const int row = blockIdx.x;
    const int tid = threadIdx.x;

    const float4 a = ((const float4*)(A + (size_t)row * D_MODEL))[tid];
    const float4 b = ((const float4*)(Bb + (size_t)row * D_MODEL))[tid];
    float4 v = make_float4(a.x + b.x, a.y + b.y, a.z + b.z, a.w + b.w);

    float sum = v.x + v.y + v.z + v.w;
    float sq = v.x * v.x + v.y * v.y + v.z * v.z + v.w * v.w;
#pragma unroll
    for (int off = 16; off > 0; off >>= 1) {
        sum += __shfl_xor_sync(0xFFFFFFFF, sum, off);
        sq  += __shfl_xor_sync(0xFFFFFFFF, sq, off);
    }
    __shared__ float ssum[8], ssq[8];
    __shared__ float s_mu, s_inv;
    const int wid = tid >> 5, lane = tid & 31;
    if (lane == 0) { ssum[wid] = sum; ssq[wid] = sq; }
    __syncthreads();
    if (tid == 0) {
        float ts = 0.f, tq2 = 0.f;
#pragma unroll
        for (int i = 0; i < 8; i++) { ts += ssum[i]; tq2 += ssq[i]; }
        const float mu = ts * (1.f / D_MODEL);
        const float var = tq2 * (1.f / D_MODEL) - mu * mu;
        s_mu = mu;
        s_inv = rsqrtf(var + EPS);
    }
    __syncthreads();
    const float mu = s_mu, inv = s_inv;

    const float4 gv = ((const float4*)g)[tid];
    const float4 bev = ((const float4*)be)[tid];
    float4 r;
    r.x = (v.x - mu) * inv * gv.x + bev.x;
    r.y = (v.y - mu) * inv * gv.y + bev.y;
    r.z = (v.z - mu) * inv * gv.z + bev.z;
    r.w = (v.w - mu) * inv * gv.w + bev.w;
    ((float4*)(out + (size_t)row * D_MODEL))[tid] = r;
    if (DUAL) {
        __half2* op = (__half2*)(outh + (size_t)row * D_MODEL);
        op[2 * tid]     = __floats2half2_rn(r.x, r.y);
        op[2 * tid + 1] = __floats2half2_rn(r.z, r.w);
    }
}

// ---------------- launch ------------------------------------------------------
extern "C" void kernel_launch(void* const* d_in, const int* in_sizes, int n_in,
                              void* d_out, int out_size)
{
    const float* x   = (const float*)d_in[0];
    const float* Wq  = (const float*)d_in[1];
    const float* bq  = (const float*)d_in[2];
    const float* Wk  = (const float*)d_in[3];
    const float* bk  = (const float*)d_in[4];
    const float* Wv  = (const float*)d_in[5];
    const float* bv  = (const float*)d_in[6];
    const float* Wo  = (const float*)d_in[7];
    const float* bo  = (const float*)d_in[8];
    const float* g1  = (const float*)d_in[9];
    const float* be1 = (const float*)d_in[10];
    const float* W1  = (const float*)d_in[11];
    const float* b1  = (const float*)d_in[12];
    const float* W2  = (const float*)d_in[13];
    const float* b2  = (const float*)d_in[14];
    const float* g2  = (const float*)d_in[15];
    const float* be2 = (const float*)d_in[16];
    float* out = (float*)d_out;

    __half *xh, *qkv, *vt, *Bqkv, *Bo, *B1, *B2, *ctx, *y1h, *hh;
    float *bqkv, *tmp, *y1;
    cudaGetSymbolAddress((void**)&xh,   g_xh);
    cudaGetSymbolAddress((void**)&qkv,  g_qkv);
    cudaGetSymbolAddress((void**)&vt,   g_vt);
    cudaGetSymbolAddress((void**)&Bqkv, g_Bqkv);
    cudaGetSymbolAddress((void**)&Bo,   g_Bo);
    cudaGetSymbolAddress((void**)&B1,   g_B1);
    cudaGetSymbolAddress((void**)&B2,   g_B2);
    cudaGetSymbolAddress((void**)&ctx,  g_ctx);
    cudaGetSymbolAddress((void**)&y1h,  g_y1h);
    cudaGetSymbolAddress((void**)&hh,   g_hh);
    cudaGetSymbolAddress((void**)&bqkv, g_bqkv);
    cudaGetSymbolAddress((void**)&tmp,  g_tmp);
    cudaGetSymbolAddress((void**)&y1,   g_y1);

    cudaFuncSetAttribute(gemm_h<128, 0, 1, 1>, cudaFuncAttributeMaxDynamicSharedMemorySize,
                         GCfg<128>::SMEM);
    cudaFuncSetAttribute(gemm_h<64, 0, 0, 0>, cudaFuncAttributeMaxDynamicSharedMemorySize,
                         GCfg<64>::SMEM);
    cudaFuncSetAttribute(gemm_h<64, 1, 1, 0>, cudaFuncAttributeMaxDynamicSharedMemorySize,
                         GCfg<64>::SMEM);

    // 1: prep (x->fp16, bias pack, all weight transposes)
    prep_kernel<<<dim3(32, 128, 7), dim3(32, 8)>>>(x, Wq, Wk, Wv, Wo, W1, W2,
                                                   bq, bk, bv,
                                                   xh, Bqkv, Bo, B1, B2, bqkv);
    // 2: fused QKV (Q,K fp16 to qkv; V transposed to vt)
    gemm_h<128, 0, 1, 1><<<dim3(QKVN / 128, ROWS / 128), 256, GCfg<128>::SMEM>>>(
        xh, Bqkv, bqkv, nullptr, qkv, vt, QKVN);
    // 3: tensor-core attention (128-row q-tiles)
    attn_mma<<<dim3(SEQ / 128, BH), 256>>>(qkv, vt, ctx);
    // 4: Wo (fp32 out)
    gemm_h<64, 0, 0, 0><<<dim3(D_MODEL / 64, ROWS / 128), 256, GCfg<64>::SMEM>>>(
        ctx, Bo, bo, tmp, nullptr, nullptr, D_MODEL);
    // 5: LN1
    add_ln_kernel<true><<<ROWS, 256>>>(x, tmp, g1, be1, y1, y1h);
    // 6: W1 + ReLU (fp16 out)  <-- ncu captures this launch
    gemm_h<64, 1, 1, 0><<<dim3(D_MODEL / 64, ROWS / 128), 256, GCfg<64>::SMEM>>>(
        y1h, B1, b1, nullptr, hh, nullptr, D_MODEL);
    // 7: W2 (fp32 out)
    gemm_h<64, 0, 0, 0><<<dim3(D_MODEL / 64, ROWS / 128), 256, GCfg<64>::SMEM>>>(
        hh, B2, b2, tmp, nullptr, nullptr, D_MODEL);
    // 8: LN2 -> output
    add_ln_kernel<false><<<ROWS, 256>>>(y1, tmp, g2, be2, out, nullptr);
}

// round 8
// speedup vs baseline: 1.1539x; 1.1539x over previous
#include <cuda_runtime.h>
#include <cuda_fp16.h>
#include <cstdint>

#define D_MODEL 1024
#define N_HEADS 16
#define D_HEAD  64
#define BATCH   4
#define SEQ     1024
#define ROWS    (BATCH * SEQ)        // 4096
#define BH      (BATCH * N_HEADS)    // 64
#define QKVN    3072
#define GK      1024
#define EPS     1e-5f

// ---------------- scratch ----------------------------------------------------
__device__ __align__(16) __half g_xh  [ROWS * D_MODEL];
__device__ __align__(16) __half g_qkv [ROWS * QKVN];
__device__ __align__(16) __half g_vt  [BH * D_HEAD * SEQ];   // V transposed [bh][d][s]
__device__ __align__(16) __half g_Bqkv[QKVN * D_MODEL];
__device__ __align__(16) __half g_Bo  [D_MODEL * D_MODEL];
__device__ __align__(16) __half g_B1  [D_MODEL * D_MODEL];
__device__ __align__(16) __half g_B2  [D_MODEL * D_MODEL];
__device__ __align__(16) __half g_ctx [ROWS * D_MODEL];
__device__ __align__(16) __half g_y1h [ROWS * D_MODEL];
__device__ __align__(16) __half g_hh  [ROWS * D_MODEL];
__device__ __align__(16) float  g_bqkv[QKVN];
__device__ __align__(16) float  g_tmp [ROWS * D_MODEL];
__device__ __align__(16) float  g_y1  [ROWS * D_MODEL];

// ---------------- helpers ----------------------------------------------------
__device__ __forceinline__ uint32_t smem_u32(const void* p) {
    uint32_t a;
    asm("{ .reg .u64 t; cvta.to.shared.u64 t, %1; cvt.u32.u64 %0, t; }" : "=r"(a) : "l"(p));
    return a;
}
#define SWZ(o) ((o) ^ (((o) >> 3) & 0x70))

__device__ __forceinline__ void cp16(uint32_t dst, const void* src) {
    asm volatile("cp.async.cg.shared.global [%0], [%1], 16;" :: "r"(dst), "l"(src) : "memory");
}
__device__ __forceinline__ void cp_commit() {
    asm volatile("cp.async.commit_group;" ::: "memory");
}
__device__ __forceinline__ void cp_wait1() {
    asm volatile("cp.async.wait_group 1;" ::: "memory");
}

__device__ __forceinline__ void ldsm4(uint32_t& r0, uint32_t& r1, uint32_t& r2, uint32_t& r3,
                                      uint32_t a) {
    asm volatile("ldmatrix.sync.aligned.m8n8.x4.shared.b16 {%0,%1,%2,%3}, [%4];"
                 : "=r"(r0), "=r"(r1), "=r"(r2), "=r"(r3) : "r"(a));
}
__device__ __forceinline__ void mma_h(float* c, const uint32_t* a, uint32_t b0, uint32_t b1) {
    asm volatile(
        "mma.sync.aligned.m16n8k16.row.col.f32.f16.f16.f32 "
        "{%0,%1,%2,%3}, {%4,%5,%6,%7}, {%8,%9}, {%0,%1,%2,%3};"
        : "+f"(c[0]), "+f"(c[1]), "+f"(c[2]), "+f"(c[3])
        : "r"(a[0]), "r"(a[1]), "r"(a[2]), "r"(a[3]), "r"(b0), "r"(b1));
}

// ---------------- fp16 GEMM: C[m][n] = A[m][k] * Bt[n][k]^T + bias -----------
// tile 128x128x64, 256 threads (8 warps: 4m x 2n), 3-stage cp.async, 2 CTAs/SM.
#define STAGE_BYTES 32768
#define GSMEM_TOTAL (3 * STAGE_BYTES)

template <int RELU, int OUTHALF, int VT>
__global__ void __launch_bounds__(256, 2) gemm_h(
    const __half* __restrict__ A, const __half* __restrict__ Bt,
    const float* __restrict__ bias, float* __restrict__ Cf,
    __half* __restrict__ Ch, __half* __restrict__ vt, int Nld)
{
    extern __shared__ char sm[];
    const uint32_t sb = smem_u32(sm);
    const int tid = threadIdx.x, wid = tid >> 5, lane = tid & 31;
    const int m0 = blockIdx.y * 128, n0 = blockIdx.x * 128;
    const int wM = (wid & 3) * 32, wN = (wid >> 2) * 64;

    float acc[2][8][4];
#pragma unroll
    for (int t = 0; t < 2; t++)
#pragma unroll
        for (int n = 0; n < 8; n++)
#pragma unroll
            for (int j = 0; j < 4; j++) acc[t][n][j] = 0.f;

    auto load_stage = [&](int s, int k0) {
        const uint32_t base = sb + (uint32_t)s * STAGE_BYTES;
#pragma unroll
        for (int i = 0; i < 4; i++) {
            int c = tid + i * 256;
            int r = c >> 3, q = c & 7;
            cp16(base + SWZ((uint32_t)(r * 128 + q * 16)),
                 A + (size_t)(m0 + r) * GK + k0 + q * 8);
        }
#pragma unroll
        for (int i = 0; i < 4; i++) {
            int c = tid + i * 256;
            int r = c >> 3, q = c & 7;
            cp16(base + 16384u + SWZ((uint32_t)(r * 128 + q * 16)),
                 Bt + (size_t)(n0 + r) * GK + k0 + q * 8);
        }
    };

    load_stage(0, 0); cp_commit();
    load_stage(1, 64); cp_commit();
    cp_wait1();
    __syncthreads();

    const int lr15 = lane & 15, l16 = (lane & 16) ? 16 : 0;
    const int bR = (lane & 7) + ((lane & 16) ? 8 : 0), b16 = (lane & 8) ? 16 : 0;

    for (int it = 0; it < 16; it++) {
        if (it + 2 < 16) load_stage((it + 2) % 3, (it + 2) * 64);
        cp_commit();

        const uint32_t aB = sb + (uint32_t)(it % 3) * STAGE_BYTES;
        const uint32_t bB = aB + 16384u;
#pragma unroll
        for (int kb = 0; kb < 4; kb++) {
            uint32_t a[2][4];
#pragma unroll
            for (int t = 0; t < 2; t++)
                ldsm4(a[t][0], a[t][1], a[t][2], a[t][3],
                      aB + SWZ((uint32_t)((wM + t * 16 + lr15) * 128 + kb * 32 + l16)));
#pragma unroll
            for (int nn = 0; nn < 4; nn++) {
                uint32_t b0, b1, b2, b3;
                ldsm4(b0, b1, b2, b3,
                      bB + SWZ((uint32_t)((wN + nn * 16 + bR) * 128 + kb * 32 + b16)));
#pragma unroll
                for (int t = 0; t < 2; t++) {
                    mma_h(acc[t][2 * nn],     a[t], b0, b1);
                    mma_h(acc[t][2 * nn + 1], a[t], b2, b3);
                }
            }
        }
        cp_wait1();
        __syncthreads();
    }

    const int tq = lane & 3, g = lane >> 2;
#pragma unroll
    for (int t = 0; t < 2; t++) {
        const int r0 = m0 + wM + t * 16 + g;
#pragma unroll
        for (int n = 0; n < 8; n++) {
            const int cc = n0 + wN + n * 8 + 2 * tq;
            const float2 bv = *(const float2*)(bias + cc);
            float v0 = acc[t][n][0] + bv.x;
            float v1 = acc[t][n][1] + bv.y;
            float v2 = acc[t][n][2] + bv.x;
            float v3 = acc[t][n][3] + bv.y;
            if (RELU) {
                v0 = fmaxf(v0, 0.f); v1 = fmaxf(v1, 0.f);
                v2 = fmaxf(v2, 0.f); v3 = fmaxf(v3, 0.f);
            }
            if (VT && n0 >= 2048) {
                const int b = r0 >> 10, s = r0 & 1023;
                const int rel = cc - 2048;
                const int h = rel >> 6, d = rel & 63;
                __half* vp = vt + ((size_t)(b * 16 + h) * 64 + d) * 1024 + s;
                vp[0]        = __float2half_rn(v0);
                vp[1024]     = __float2half_rn(v1);
                vp[8]        = __float2half_rn(v2);
                vp[1024 + 8] = __float2half_rn(v3);
            } else if (OUTHALF) {
                *(__half2*)(Ch + (size_t)r0 * Nld + cc)       = __floats2half2_rn(v0, v1);
                *(__half2*)(Ch + (size_t)(r0 + 8) * Nld + cc) = __floats2half2_rn(v2, v3);
            } else {
                *(float2*)(Cf + (size_t)r0 * Nld + cc)       = make_float2(v0, v1);
                *(float2*)(Cf + (size_t)(r0 + 8) * Nld + cc) = make_float2(v2, v3);
            }
        }
    }
}

// ---------------- tensor-core flash attention (R6-proven, 64-row q-tiles) ----
__global__ void __launch_bounds__(128) attn_mma(const __half* __restrict__ qkv,
                                               const __half* __restrict__ vt,
                                               __half* __restrict__ ctx)
{
    __shared__ __align__(16) __half Qs[64 * 64];
    __shared__ __align__(16) __half Ks[2][64 * 64];
    __shared__ __align__(16) __half Vts[2][64 * 64];

    const int bh = blockIdx.y, b = bh >> 4, h = bh & 15;
    const int s0 = blockIdx.x * 64;
    const int tid = threadIdx.x, wid = tid >> 5, lane = tid & 31;
    const uint32_t qB = smem_u32(Qs);
    const uint32_t kB0 = smem_u32(Ks), vB0 = smem_u32(Vts);

#pragma unroll
    for (int i = 0; i < 4; i++) {
        int c = tid + i * 128;
        int r = c >> 3, q = c & 7;
        cp16(qB + SWZ((uint32_t)(r * 128 + q * 16)),
             qkv + (size_t)(b * SEQ + s0 + r) * QKVN + h * 64 + q * 8);
    }
    auto load_kv = [&](int buf, int t) {
#pragma unroll
        for (int i = 0; i < 4; i++) {
            int c = tid + i * 128;
            int r = c >> 3, q = c & 7;
            cp16(kB0 + buf * 8192u + SWZ((uint32_t)(r * 128 + q * 16)),
                 qkv + (size_t)(b * SEQ + t * 64 + r) * QKVN + 1024 + h * 64 + q * 8);
            cp16(vB0 + buf * 8192u + SWZ((uint32_t)(r * 128 + q * 16)),
                 vt + ((size_t)bh * 64 + r) * SEQ + t * 64 + q * 8);
        }
    };
    load_kv(0, 0); cp_commit();
    load_kv(1, 1); cp_commit();
    cp_wait1();
    __syncthreads();

    const int lr15 = lane & 15, l16 = (lane & 16) ? 16 : 0;
    const int bR = (lane & 7) + ((lane & 16) ? 8 : 0), b16 = (lane & 8) ? 16 : 0;

    uint32_t aq[4][4];
    const __half2 sc = __floats2half2_rn(0.125f, 0.125f);
#pragma unroll
    for (int kb = 0; kb < 4; kb++) {
        ldsm4(aq[kb][0], aq[kb][1], aq[kb][2], aq[kb][3],
              qB + SWZ((uint32_t)((wid * 16 + lr15) * 128 + kb * 32 + l16)));
#pragma unroll
        for (int j = 0; j < 4; j++) {
            __half2 v = *reinterpret_cast<__half2*>(&aq[kb][j]);
            v = __hmul2(v, sc);
            aq[kb][j] = *reinterpret_cast<uint32_t*>(&v);
        }
    }

    float o[8][4];
#pragma unroll
    for (int j = 0; j < 8; j++)
#pragma unroll
        for (int k = 0; k < 4; k++) o[j][k] = 0.f;
    float mr0 = -1e30f, mr1 = -1e30f, lp0 = 0.f, lp1 = 0.f;

    for (int t = 0; t < 16; t++) {
        const uint32_t kB = kB0 + (t & 1) * 8192u;
        const uint32_t vB = vB0 + (t & 1) * 8192u;

        float s[8][4];
#pragma unroll
        for (int j = 0; j < 8; j++)
#pragma unroll
            for (int k = 0; k < 4; k++) s[j][k] = 0.f;
#pragma unroll
        for (int kb = 0; kb < 4; kb++) {
#pragma unroll
            for (int nn = 0; nn < 4; nn++) {
                uint32_t b0, b1, b2, b3;
                ldsm4(b0, b1, b2, b3,
                      kB + SWZ((uint32_t)((nn * 16 + bR) * 128 + kb * 32 + b16)));
                mma_h(s[2 * nn],     aq[kb], b0, b1);
                mma_h(s[2 * nn + 1], aq[kb], b2, b3);
            }
        }

        float mt0 = s[0][0], mt1 = s[0][2];
#pragma unroll
        for (int j = 0; j < 8; j++) {
            mt0 = fmaxf(mt0, fmaxf(s[j][0], s[j][1]));
            mt1 = fmaxf(mt1, fmaxf(s[j][2], s[j][3]));
        }
#pragma unroll
        for (int off = 1; off <= 2; off <<= 1) {
            mt0 = fmaxf(mt0, __shfl_xor_sync(0xFFFFFFFF, mt0, off));
            mt1 = fmaxf(mt1, __shfl_xor_sync(0xFFFFFFFF, mt1, off));
        }
        const float nm0 = fmaxf(mr0, mt0), nm1 = fmaxf(mr1, mt1);
        const float al0 = __expf(mr0 - nm0), al1 = __expf(mr1 - nm1);
        mr0 = nm0; mr1 = nm1;
        float ps0 = 0.f, ps1 = 0.f;
#pragma unroll
        for (int j = 0; j < 8; j++) {
            s[j][0] = __expf(s[j][0] - nm0);
            s[j][1] = __expf(s[j][1] - nm0);
            s[j][2] = __expf(s[j][2] - nm1);
            s[j][3] = __expf(s[j][3] - nm1);
            ps0 += s[j][0] + s[j][1];
            ps1 += s[j][2] + s[j][3];
        }
        lp0 = lp0 * al0 + ps0;
        lp1 = lp1 * al1 + ps1;
#pragma unroll
        for (int j = 0; j < 8; j++) {
            o[j][0] *= al0; o[j][1] *= al0;
            o[j][2] *= al1; o[j][3] *= al1;
        }

#pragma unroll
        for (int kb = 0; kb < 4; kb++) {
            uint32_t pa[4];
            __half2 p0 = __floats2half2_rn(s[2 * kb][0], s[2 * kb][1]);
            __half2 p1 = __floats2half2_rn(s[2 * kb][2], s[2 * kb][3]);
            __half2 p2 = __floats2half2_rn(s[2 * kb + 1][0], s[2 * kb + 1][1]);
            __half2 p3 = __floats2half2_rn(s[2 * kb + 1][2], s[2 * kb + 1][3]);
            pa[0] = *reinterpret_cast<uint32_t*>(&p0);
            pa[1] = *reinterpret_cast<uint32_t*>(&p1);
            pa[2] = *reinterpret_cast<uint32_t*>(&p2);
            pa[3] = *reinterpret_cast<uint32_t*>(&p3);
#pragma unroll
            for (int nn = 0; nn < 4; nn++) {
                uint32_t b0, b1, b2, b3;
                ldsm4(b0, b1, b2, b3,
                      vB + SWZ((uint32_t)((nn * 16 + bR) * 128 + kb * 32 + b16)));
                mma_h(o[2 * nn],     pa, b0, b1);
                mma_h(o[2 * nn + 1], pa, b2, b3);
            }
        }

        __syncthreads();
        if (t + 2 < 16) load_kv(t & 1, t + 2);
        cp_commit();
        cp_wait1();
        __syncthreads();
    }

#pragma unroll
    for (int off = 1; off <= 2; off <<= 1) {
        lp0 += __shfl_xor_sync(0xFFFFFFFF, lp0, off);
        lp1 += __shfl_xor_sync(0xFFFFFFFF, lp1, off);
    }
    const float i0 = 1.f / lp0, i1 = 1.f / lp1;
    const int g = lane >> 2, tq = lane & 3;
    const int r0 = b * SEQ + s0 + wid * 16 + g;
#pragma unroll
    for (int j = 0; j < 8; j++) {
        const int cc = h * 64 + 8 * j + 2 * tq;
        *(__half2*)(ctx + (size_t)r0 * D_MODEL + cc) =
            __floats2half2_rn(o[j][0] * i0, o[j][1] * i0);
        *(__half2*)(ctx + (size_t)(r0 + 8) * D_MODEL + cc) =
            __floats2half2_rn(o[j][2] * i1, o[j][3] * i1);
    }
}

// ---------------- prep kernels (R6-proven split) ------------------------------
__global__ void prep_x(const float* __restrict__ x, __half* __restrict__ xh) {
    const size_t i = (size_t)blockIdx.x * 256 + threadIdx.x;
    const float4 v = ((const float4*)x)[i];
    __half2* o = (__half2*)xh;
    o[2 * i]     = __floats2half2_rn(v.x, v.y);
    o[2 * i + 1] = __floats2half2_rn(v.z, v.w);
}

__global__ void pack_bias(const float* __restrict__ bq, const float* __restrict__ bk,
                          const float* __restrict__ bv, float* __restrict__ o) {
    const int t = threadIdx.x;
    const float* src = (blockIdx.x == 0) ? bq : (blockIdx.x == 1) ? bk : bv;
    o[blockIdx.x * 1024 + t] = src[t];
}

__global__ void prep_wqkv(const float* __restrict__ Wq, const float* __restrict__ Wk,
                          const float* __restrict__ Wv, __half* __restrict__ Bqkv) {
    __shared__ float t[32][33];
    const int z = blockIdx.z;
    const float* W = (z == 0) ? Wq : (z == 1) ? Wk : Wv;
    __half* out = Bqkv + (size_t)z * 1024 * 1024;
    const int hh = blockIdx.x >> 1, d0 = (blockIdx.x & 1) * 32;
    const int k0 = blockIdx.y * 32;
    const int tx = threadIdx.x, ty = threadIdx.y;
#pragma unroll
    for (int i = 0; i < 32; i += 8)
        t[ty + i][tx] = W[((size_t)hh * 1024 + k0 + ty + i) * 64 + d0 + tx];
    __syncthreads();
#pragma unroll
    for (int i = 0; i < 32; i += 8)
        out[(size_t)(hh * 64 + d0 + ty + i) * 1024 + k0 + tx] = __float2half_rn(t[tx][ty + i]);
}

__global__ void prep_w(const float* __restrict__ Wo, const float* __restrict__ W1,
                       const float* __restrict__ W2,
                       __half* __restrict__ Bo, __half* __restrict__ B1,
                       __half* __restrict__ B2) {
    __shared__ float t[32][33];
    const int z = blockIdx.z;
    const float* W = (z == 0) ? Wo : (z == 1) ? W1 : W2;
    __half* out = (z == 0) ? Bo : (z == 1) ? B1 : B2;
    const int n0 = blockIdx.x * 32, k0 = blockIdx.y * 32;
    const int tx = threadIdx.x, ty = threadIdx.y;
#pragma unroll
    for (int i = 0; i < 32; i += 8)
        t[ty + i][tx] = W[(size_t)(k0 + ty + i) * 1024 + n0 + tx];
    __syncthreads();
#pragma unroll
    for (int i = 0; i < 32; i += 8)
        out[(size_t)(n0 + ty + i) * 1024 + k0 + tx] = __float2half_rn(t[tx][ty + i]);
}

// ---------------- residual + LayerNorm ---------------------------------------
template <bool DUAL>
__global__ __launch_bounds__(256) void add_ln_kernel(
    const float* __restrict__ A, const float* __restrict__ Bb,
    const float* __restrict__ g, const float* __restrict__ be,
    float* __restrict__ out, __half* __restrict__ outh)
{
    const int row = blockIdx.x;
    const int tid = threadIdx.x;

    const float4 a = ((const float4*)(A + (size_t)row * D_MODEL))[tid];
    const float4 b = ((const float4*)(Bb + (size_t)row * D_MODEL))[tid];
    float4 v = make_float4(a.x + b.x, a.y + b.y, a.z + b.z, a.w + b.w);

    float sum = v.x + v.y + v.z + v.w;
    float sq = v.x * v.x + v.y * v.y + v.z * v.z + v.w * v.w;
#pragma unroll
    for (int off = 16; off > 0; off >>= 1) {
        sum += __shfl_xor_sync(0xFFFFFFFF, sum, off);
        sq  += __shfl_xor_sync(0xFFFFFFFF, sq, off);
    }
    __shared__ float ssum[8], ssq[8];
    __shared__ float s_mu, s_inv;
    const int wid = tid >> 5, lane = tid & 31;
    if (lane == 0) { ssum[wid] = sum; ssq[wid] = sq; }
    __syncthreads();
    if (tid == 0) {
        float ts = 0.f, tq2 = 0.f;
#pragma unroll
        for (int i = 0; i < 8; i++) { ts += ssum[i]; tq2 += ssq[i]; }
        const float mu = ts * (1.f / D_MODEL);
        const float var = tq2 * (1.f / D_MODEL) - mu * mu;
        s_mu = mu;
        s_inv = rsqrtf(var + EPS);
    }
    __syncthreads();
    const float mu = s_mu, inv = s_inv;

    const float4 gv = ((const float4*)g)[tid];
    const float4 bev = ((const float4*)be)[tid];
    float4 r;
    r.x = (v.x - mu) * inv * gv.x + bev.x;
    r.y = (v.y - mu) * inv * gv.y + bev.y;
    r.z = (v.z - mu) * inv * gv.z + bev.z;
    r.w = (v.w - mu) * inv * gv.w + bev.w;
    ((float4*)(out + (size_t)row * D_MODEL))[tid] = r;
    if (DUAL) {
        __half2* op = (__half2*)(outh + (size_t)row * D_MODEL);
        op[2 * tid]     = __floats2half2_rn(r.x, r.y);
        op[2 * tid + 1] = __floats2half2_rn(r.z, r.w);
    }
}

// ---------------- launch ------------------------------------------------------
extern "C" void kernel_launch(void* const* d_in, const int* in_sizes, int n_in,
                              void* d_out, int out_size)
{
    const float* x   = (const float*)d_in[0];
    const float* Wq  = (const float*)d_in[1];
    const float* bq  = (const float*)d_in[2];
    const float* Wk  = (const float*)d_in[3];
    const float* bk  = (const float*)d_in[4];
    const float* Wv  = (const float*)d_in[5];
    const float* bv  = (const float*)d_in[6];
    const float* Wo  = (const float*)d_in[7];
    const float* bo  = (const float*)d_in[8];
    const float* g1  = (const float*)d_in[9];
    const float* be1 = (const float*)d_in[10];
    const float* W1  = (const float*)d_in[11];
    const float* b1  = (const float*)d_in[12];
    const float* W2  = (const float*)d_in[13];
    const float* b2  = (const float*)d_in[14];
    const float* g2  = (const float*)d_in[15];
    const float* be2 = (const float*)d_in[16];
    float* out = (float*)d_out;

    __half *xh, *qkv, *vt, *Bqkv, *Bo, *B1, *B2, *ctx, *y1h, *hh;
    float *bqkv, *tmp, *y1;
    cudaGetSymbolAddress((void**)&xh,   g_xh);
    cudaGetSymbolAddress((void**)&qkv,  g_qkv);
    cudaGetSymbolAddress((void**)&vt,   g_vt);
    cudaGetSymbolAddress((void**)&Bqkv, g_Bqkv);
    cudaGetSymbolAddress((void**)&Bo,   g_Bo);
    cudaGetSymbolAddress((void**)&B1,   g_B1);
    cudaGetSymbolAddress((void**)&B2,   g_B2);
    cudaGetSymbolAddress((void**)&ctx,  g_ctx);
    cudaGetSymbolAddress((void**)&y1h,  g_y1h);
    cudaGetSymbolAddress((void**)&hh,   g_hh);
    cudaGetSymbolAddress((void**)&bqkv, g_bqkv);
    cudaGetSymbolAddress((void**)&tmp,  g_tmp);
    cudaGetSymbolAddress((void**)&y1,   g_y1);

    cudaFuncSetAttribute(gemm_h<0, 0, 0>, cudaFuncAttributeMaxDynamicSharedMemorySize, GSMEM_TOTAL);
    cudaFuncSetAttribute(gemm_h<0, 1, 1>, cudaFuncAttributeMaxDynamicSharedMemorySize, GSMEM_TOTAL);
    cudaFuncSetAttribute(gemm_h<1, 1, 0>, cudaFuncAttributeMaxDynamicSharedMemorySize, GSMEM_TOTAL);

    // 1-4: prep
    prep_x<<<ROWS, 256>>>(x, xh);
    pack_bias<<<3, 1024>>>(bq, bk, bv, bqkv);
    prep_wqkv<<<dim3(32, 32, 3), dim3(32, 8)>>>(Wq, Wk, Wv, Bqkv);
    prep_w<<<dim3(32, 32, 3), dim3(32, 8)>>>(Wo, W1, W2, Bo, B1, B2);
    // 5: fused QKV (Q,K fp16 to qkv; V transposed to vt)
    gemm_h<0, 1, 1><<<dim3(QKVN / 128, ROWS / 128), 256, GSMEM_TOTAL>>>(
        xh, Bqkv, bqkv, nullptr, qkv, vt, QKVN);
    // 6: tensor-core attention   <-- ncu captures this launch
    attn_mma<<<dim3(SEQ / 64, BH), 128>>>(qkv, vt, ctx);
    // 7: Wo (fp32 out)
    gemm_h<0, 0, 0><<<dim3(D_MODEL / 128, ROWS / 128), 256, GSMEM_TOTAL>>>(
        ctx, Bo, bo, tmp, nullptr, nullptr, D_MODEL);
    // 8: LN1
    add_ln_kernel<true><<<ROWS, 256>>>(x, tmp, g1, be1, y1, y1h);
    // 9: W1 + ReLU (fp16 out)
    gemm_h<1, 1, 0><<<dim3(D_MODEL / 128, ROWS / 128), 256, GSMEM_TOTAL>>>(
        y1h, B1, b1, nullptr, hh, nullptr, D_MODEL);
    // 10: W2 (fp32 out)
    gemm_h<0, 0, 0><<<dim3(D_MODEL / 128, ROWS / 128), 256, GSMEM_TOTAL>>>(
        hh, B2, b2, tmp, nullptr, nullptr, D_MODEL);
    // 11: LN2 -> output
    add_ln_kernel<false><<<ROWS, 256>>>(y1, tmp, g2, be2, out, nullptr);
}

// round 9
// speedup vs baseline: 1.1545x; 1.0005x over previous
#include <cuda_runtime.h>
#include <cuda_fp16.h>
#include <cstdint>

#define D_MODEL 1024
#define N_HEADS 16
#define D_HEAD  64
#define BATCH   4
#define SEQ     1024
#define ROWS    (BATCH * SEQ)        // 4096
#define BH      (BATCH * N_HEADS)    // 64
#define QKVN    3072
#define GK      1024
#define EPS     1e-5f

// ---------------- scratch ----------------------------------------------------
__device__ __align__(16) __half g_xh  [ROWS * D_MODEL];
__device__ __align__(16) __half g_qkv [ROWS * QKVN];
__device__ __align__(16) __half g_vt  [BH * D_HEAD * SEQ];   // V transposed [bh][d][s]
__device__ __align__(16) __half g_Bqkv[QKVN * D_MODEL];
__device__ __align__(16) __half g_Bo  [D_MODEL * D_MODEL];
__device__ __align__(16) __half g_B1  [D_MODEL * D_MODEL];
__device__ __align__(16) __half g_B2  [D_MODEL * D_MODEL];
__device__ __align__(16) __half g_ctx [ROWS * D_MODEL];
__device__ __align__(16) __half g_y1h [ROWS * D_MODEL];
__device__ __align__(16) __half g_hh  [ROWS * D_MODEL];
__device__ __align__(16) float  g_bqkv[QKVN];
__device__ __align__(16) float  g_tmp [ROWS * D_MODEL];
__device__ __align__(16) float  g_y1  [ROWS * D_MODEL];

// ---------------- helpers ----------------------------------------------------
__device__ __forceinline__ uint32_t smem_u32(const void* p) {
    uint32_t a;
    asm("{ .reg .u64 t; cvta.to.shared.u64 t, %1; cvt.u32.u64 %0, t; }" : "=r"(a) : "l"(p));
    return a;
}
#define SWZ(o) ((o) ^ (((o) >> 3) & 0x70))

__device__ __forceinline__ void cp16(uint32_t dst, const void* src) {
    asm volatile("cp.async.cg.shared.global [%0], [%1], 16;" :: "r"(dst), "l"(src) : "memory");
}
__device__ __forceinline__ void cp_commit() {
    asm volatile("cp.async.commit_group;" ::: "memory");
}
__device__ __forceinline__ void cp_wait1() {
    asm volatile("cp.async.wait_group 1;" ::: "memory");
}

__device__ __forceinline__ void ldsm4(uint32_t& r0, uint32_t& r1, uint32_t& r2, uint32_t& r3,
                                      uint32_t a) {
    asm volatile("ldmatrix.sync.aligned.m8n8.x4.shared.b16 {%0,%1,%2,%3}, [%4];"
                 : "=r"(r0), "=r"(r1), "=r"(r2), "=r"(r3) : "r"(a));
}
__device__ __forceinline__ void mma_h(float* c, const uint32_t* a, uint32_t b0, uint32_t b1) {
    asm volatile(
        "mma.sync.aligned.m16n8k16.row.col.f32.f16.f16.f32 "
        "{%0,%1,%2,%3}, {%4,%5,%6,%7}, {%8,%9}, {%0,%1,%2,%3};"
        : "+f"(c[0]), "+f"(c[1]), "+f"(c[2]), "+f"(c[3])
        : "r"(a[0]), "r"(a[1]), "r"(a[2]), "r"(a[3]), "r"(b0), "r"(b1));
}

// ---------------- fp16 GEMM: C[m][n] = A[m][k] * Bt[n][k]^T + bias -----------
// tile 128x256x64, 512 threads (16 warps: 4m x 4n), 3-stage cp.async.
// Per-warp fragment pattern identical to the proven 8-warp kernel.
#define STAGE_BYTES 49152                     // A 16KB + B 32KB
#define GSMEM_TOTAL (3 * STAGE_BYTES)         // 147456

template <int RELU, int OUTHALF, int VT>
__global__ void __launch_bounds__(512, 1) gemm_h(
    const __half* __restrict__ A, const __half* __restrict__ Bt,
    const float* __restrict__ bias, float* __restrict__ Cf,
    __half* __restrict__ Ch, __half* __restrict__ vt, int Nld)
{
    extern __shared__ char sm[];
    const uint32_t sb = smem_u32(sm);
    const int tid = threadIdx.x, wid = tid >> 5, lane = tid & 31;
    const int m0 = blockIdx.y * 128, n0 = blockIdx.x * 256;
    const int wM = (wid & 3) * 32, wN = (wid >> 2) * 64;

    float acc[2][8][4];
#pragma unroll
    for (int t = 0; t < 2; t++)
#pragma unroll
        for (int n = 0; n < 8; n++)
#pragma unroll
            for (int j = 0; j < 4; j++) acc[t][n][j] = 0.f;

    auto load_stage = [&](int s, int k0) {
        const uint32_t base = sb + (uint32_t)s * STAGE_BYTES;
#pragma unroll
        for (int i = 0; i < 2; i++) {           // A: 1024 16B-chunks
            int c = tid + i * 512;
            int r = c >> 3, q = c & 7;
            cp16(base + SWZ((uint32_t)(r * 128 + q * 16)),
                 A + (size_t)(m0 + r) * GK + k0 + q * 8);
        }
#pragma unroll
        for (int i = 0; i < 4; i++) {           // B: 2048 16B-chunks (256 rows)
            int c = tid + i * 512;
            int r = c >> 3, q = c & 7;
            cp16(base + 16384u + SWZ((uint32_t)(r * 128 + q * 16)),
                 Bt + (size_t)(n0 + r) * GK + k0 + q * 8);
        }
    };

    load_stage(0, 0); cp_commit();
    load_stage(1, 64); cp_commit();
    cp_wait1();
    __syncthreads();

    const int lr15 = lane & 15, l16 = (lane & 16) ? 16 : 0;
    const int bR = (lane & 7) + ((lane & 16) ? 8 : 0), b16 = (lane & 8) ? 16 : 0;

    for (int it = 0; it < 16; it++) {
        if (it + 2 < 16) load_stage((it + 2) % 3, (it + 2) * 64);
        cp_commit();

        const uint32_t aB = sb + (uint32_t)(it % 3) * STAGE_BYTES;
        const uint32_t bB = aB + 16384u;
#pragma unroll
        for (int kb = 0; kb < 4; kb++) {
            uint32_t a[2][4];
#pragma unroll
            for (int t = 0; t < 2; t++)
                ldsm4(a[t][0], a[t][1], a[t][2], a[t][3],
                      aB + SWZ((uint32_t)((wM + t * 16 + lr15) * 128 + kb * 32 + l16)));
#pragma unroll
            for (int nn = 0; nn < 4; nn++) {
                uint32_t b0, b1, b2, b3;
                ldsm4(b0, b1, b2, b3,
                      bB + SWZ((uint32_t)((wN + nn * 16 + bR) * 128 + kb * 32 + b16)));
#pragma unroll
                for (int t = 0; t < 2; t++) {
                    mma_h(acc[t][2 * nn],     a[t], b0, b1);
                    mma_h(acc[t][2 * nn + 1], a[t], b2, b3);
                }
            }
        }
        cp_wait1();
        __syncthreads();
    }

    const int tq = lane & 3, g = lane >> 2;
#pragma unroll
    for (int t = 0; t < 2; t++) {
        const int r0 = m0 + wM + t * 16 + g;
#pragma unroll
        for (int n = 0; n < 8; n++) {
            const int cc = n0 + wN + n * 8 + 2 * tq;
            const float2 bv = *(const float2*)(bias + cc);
            float v0 = acc[t][n][0] + bv.x;
            float v1 = acc[t][n][1] + bv.y;
            float v2 = acc[t][n][2] + bv.x;
            float v3 = acc[t][n][3] + bv.y;
            if (RELU) {
                v0 = fmaxf(v0, 0.f); v1 = fmaxf(v1, 0.f);
                v2 = fmaxf(v2, 0.f); v3 = fmaxf(v3, 0.f);
            }
            if (VT && cc >= 2048) {
                const int b = r0 >> 10, s = r0 & 1023;
                const int rel = cc - 2048;
                const int h = rel >> 6, d = rel & 63;
                __half* vp = vt + ((size_t)(b * 16 + h) * 64 + d) * 1024 + s;
                vp[0]        = __float2half_rn(v0);
                vp[1024]     = __float2half_rn(v1);
                vp[8]        = __float2half_rn(v2);
                vp[1024 + 8] = __float2half_rn(v3);
            } else if (OUTHALF) {
                *(__half2*)(Ch + (size_t)r0 * Nld + cc)       = __floats2half2_rn(v0, v1);
                *(__half2*)(Ch + (size_t)(r0 + 8) * Nld + cc) = __floats2half2_rn(v2, v3);
            } else {
                *(float2*)(Cf + (size_t)r0 * Nld + cc)       = make_float2(v0, v1);
                *(float2*)(Cf + (size_t)(r0 + 8) * Nld + cc) = make_float2(v2, v3);
            }
        }
    }
}

// ---------------- tensor-core flash attention (R6-proven, 64-row q-tiles) ----
__global__ void __launch_bounds__(128) attn_mma(const __half* __restrict__ qkv,
                                               const __half* __restrict__ vt,
                                               __half* __restrict__ ctx)
{
    __shared__ __align__(16) __half Qs[64 * 64];
    __shared__ __align__(16) __half Ks[2][64 * 64];
    __shared__ __align__(16) __half Vts[2][64 * 64];

    const int bh = blockIdx.y, b = bh >> 4, h = bh & 15;
    const int s0 = blockIdx.x * 64;
    const int tid = threadIdx.x, wid = tid >> 5, lane = tid & 31;
    const uint32_t qB = smem_u32(Qs);
    const uint32_t kB0 = smem_u32(Ks), vB0 = smem_u32(Vts);

#pragma unroll
    for (int i = 0; i < 4; i++) {
        int c = tid + i * 128;
        int r = c >> 3, q = c & 7;
        cp16(qB + SWZ((uint32_t)(r * 128 + q * 16)),
             qkv + (size_t)(b * SEQ + s0 + r) * QKVN + h * 64 + q * 8);
    }
    auto load_kv = [&](int buf, int t) {
#pragma unroll
        for (int i = 0; i < 4; i++) {
            int c = tid + i * 128;
            int r = c >> 3, q = c & 7;
            cp16(kB0 + buf * 8192u + SWZ((uint32_t)(r * 128 + q * 16)),
                 qkv + (size_t)(b * SEQ + t * 64 + r) * QKVN + 1024 + h * 64 + q * 8);
            cp16(vB0 + buf * 8192u + SWZ((uint32_t)(r * 128 + q * 16)),
                 vt + ((size_t)bh * 64 + r) * SEQ + t * 64 + q * 8);
        }
    };
    load_kv(0, 0); cp_commit();
    load_kv(1, 1); cp_commit();
    cp_wait1();
    __syncthreads();

    const int lr15 = lane & 15, l16 = (lane & 16) ? 16 : 0;
    const int bR = (lane & 7) + ((lane & 16) ? 8 : 0), b16 = (lane & 8) ? 16 : 0;

    uint32_t aq[4][4];
    const __half2 sc = __floats2half2_rn(0.125f, 0.125f);
#pragma unroll
    for (int kb = 0; kb < 4; kb++) {
        ldsm4(aq[kb][0], aq[kb][1], aq[kb][2], aq[kb][3],
              qB + SWZ((uint32_t)((wid * 16 + lr15) * 128 + kb * 32 + l16)));
#pragma unroll
        for (int j = 0; j < 4; j++) {
            __half2 v = *reinterpret_cast<__half2*>(&aq[kb][j]);
            v = __hmul2(v, sc);
            aq[kb][j] = *reinterpret_cast<uint32_t*>(&v);
        }
    }

    float o[8][4];
#pragma unroll
    for (int j = 0; j < 8; j++)
#pragma unroll
        for (int k = 0; k < 4; k++) o[j][k] = 0.f;
    float mr0 = -1e30f, mr1 = -1e30f, lp0 = 0.f, lp1 = 0.f;

    for (int t = 0; t < 16; t++) {
        const uint32_t kB = kB0 + (t & 1) * 8192u;
        const uint32_t vB = vB0 + (t & 1) * 8192u;

        float s[8][4];
#pragma unroll
        for (int j = 0; j < 8; j++)
#pragma unroll
            for (int k = 0; k < 4; k++) s[j][k] = 0.f;
#pragma unroll
        for (int kb = 0; kb < 4; kb++) {
#pragma unroll
            for (int nn = 0; nn < 4; nn++) {
                uint32_t b0, b1, b2, b3;
                ldsm4(b0, b1, b2, b3,
                      kB + SWZ((uint32_t)((nn * 16 + bR) * 128 + kb * 32 + b16)));
                mma_h(s[2 * nn],     aq[kb], b0, b1);
                mma_h(s[2 * nn + 1], aq[kb], b2, b3);
            }
        }

        float mt0 = s[0][0], mt1 = s[0][2];
#pragma unroll
        for (int j = 0; j < 8; j++) {
            mt0 = fmaxf(mt0, fmaxf(s[j][0], s[j][1]));
            mt1 = fmaxf(mt1, fmaxf(s[j][2], s[j][3]));
        }
#pragma unroll
        for (int off = 1; off <= 2; off <<= 1) {
            mt0 = fmaxf(mt0, __shfl_xor_sync(0xFFFFFFFF, mt0, off));
            mt1 = fmaxf(mt1, __shfl_xor_sync(0xFFFFFFFF, mt1, off));
        }
        const float nm0 = fmaxf(mr0, mt0), nm1 = fmaxf(mr1, mt1);
        const float al0 = __expf(mr0 - nm0), al1 = __expf(mr1 - nm1);
        mr0 = nm0; mr1 = nm1;
        float ps0 = 0.f, ps1 = 0.f;
#pragma unroll
        for (int j = 0; j < 8; j++) {
            s[j][0] = __expf(s[j][0] - nm0);
            s[j][1] = __expf(s[j][1] - nm0);
            s[j][2] = __expf(s[j][2] - nm1);
            s[j][3] = __expf(s[j][3] - nm1);
            ps0 += s[j][0] + s[j][1];
            ps1 += s[j][2] + s[j][3];
        }
        lp0 = lp0 * al0 + ps0;
        lp1 = lp1 * al1 + ps1;
#pragma unroll
        for (int j = 0; j < 8; j++) {
            o[j][0] *= al0; o[j][1] *= al0;
            o[j][2] *= al1; o[j][3] *= al1;
        }

#pragma unroll
        for (int kb = 0; kb < 4; kb++) {
            uint32_t pa[4];
            __half2 p0 = __floats2half2_rn(s[2 * kb][0], s[2 * kb][1]);
            __half2 p1 = __floats2half2_rn(s[2 * kb][2], s[2 * kb][3]);
            __half2 p2 = __floats2half2_rn(s[2 * kb + 1][0], s[2 * kb + 1][1]);
            __half2 p3 = __floats2half2_rn(s[2 * kb + 1][2], s[2 * kb + 1][3]);
            pa[0] = *reinterpret_cast<uint32_t*>(&p0);
            pa[1] = *reinterpret_cast<uint32_t*>(&p1);
            pa[2] = *reinterpret_cast<uint32_t*>(&p2);
            pa[3] = *reinterpret_cast<uint32_t*>(&p3);
#pragma unroll
            for (int nn = 0; nn < 4; nn++) {
                uint32_t b0, b1, b2, b3;
                ldsm4(b0, b1, b2, b3,
                      vB + SWZ((uint32_t)((nn * 16 + bR) * 128 + kb * 32 + b16)));
                mma_h(o[2 * nn],     pa, b0, b1);
                mma_h(o[2 * nn + 1], pa, b2, b3);
            }
        }

        __syncthreads();
        if (t + 2 < 16) load_kv(t & 1, t + 2);
        cp_commit();
        cp_wait1();
        __syncthreads();
    }

#pragma unroll
    for (int off = 1; off <= 2; off <<= 1) {
        lp0 += __shfl_xor_sync(0xFFFFFFFF, lp0, off);
        lp1 += __shfl_xor_sync(0xFFFFFFFF, lp1, off);
    }
    const float i0 = 1.f / lp0, i1 = 1.f / lp1;
    const int g = lane >> 2, tq = lane & 3;
    const int r0 = b * SEQ + s0 + wid * 16 + g;
#pragma unroll
    for (int j = 0; j < 8; j++) {
        const int cc = h * 64 + 8 * j + 2 * tq;
        *(__half2*)(ctx + (size_t)r0 * D_MODEL + cc) =
            __floats2half2_rn(o[j][0] * i0, o[j][1] * i0);
        *(__half2*)(ctx + (size_t)(r0 + 8) * D_MODEL + cc) =
            __floats2half2_rn(o[j][2] * i1, o[j][3] * i1);
    }
}

// ---------------- prep kernels ------------------------------------------------
__global__ void prep_x(const float* __restrict__ x, __half* __restrict__ xh) {
    const size_t i = (size_t)blockIdx.x * 256 + threadIdx.x;
    const float4 v = ((const float4*)x)[i];
    __half2* o = (__half2*)xh;
    o[2 * i]     = __floats2half2_rn(v.x, v.y);
    o[2 * i + 1] = __floats2half2_rn(v.z, v.w);
}

__global__ void pack_bias(const float* __restrict__ bq, const float* __restrict__ bk,
                          const float* __restrict__ bv, float* __restrict__ o) {
    const int t = threadIdx.x;
    const float* src = (blockIdx.x == 0) ? bq : (blockIdx.x == 1) ? bk : bv;
    o[blockIdx.x * 1024 + t] = src[t];
}

// z=0..2: Wq/Wk/Wv per-head transpose; z=3..5: Wo/W1/W2 transpose.
__global__ void prep_weights(const float* __restrict__ Wq, const float* __restrict__ Wk,
                             const float* __restrict__ Wv,
                             const float* __restrict__ Wo, const float* __restrict__ W1,
                             const float* __restrict__ W2,
                             __half* __restrict__ Bqkv, __half* __restrict__ Bo,
                             __half* __restrict__ B1, __half* __restrict__ B2) {
    __shared__ float t[32][33];
    const int z = blockIdx.z;
    const int tx = threadIdx.x, ty = threadIdx.y;
    if (z < 3) {
        const float* W = (z == 0) ? Wq : (z == 1) ? Wk : Wv;
        __half* out = Bqkv + (size_t)z * 1024 * 1024;
        const int hh = blockIdx.x >> 1, d0 = (blockIdx.x & 1) * 32;
        const int k0 = blockIdx.y * 32;
#pragma unroll
        for (int i = 0; i < 32; i += 8)
            t[ty + i][tx] = W[((size_t)hh * 1024 + k0 + ty + i) * 64 + d0 + tx];
        __syncthreads();
#pragma unroll
        for (int i = 0; i < 32; i += 8)
            out[(size_t)(hh * 64 + d0 + ty + i) * 1024 + k0 + tx] =
                __float2half_rn(t[tx][ty + i]);
    } else {
        const float* W = (z == 3) ? Wo : (z == 4) ? W1 : W2;
        __half* out = (z == 3) ? Bo : (z == 4) ? B1 : B2;
        const int n0 = blockIdx.x * 32, k0 = blockIdx.y * 32;
#pragma unroll
        for (int i = 0; i < 32; i += 8)
            t[ty + i][tx] = W[(size_t)(k0 + ty + i) * 1024 + n0 + tx];
        __syncthreads();
#pragma unroll
        for (int i = 0; i < 32; i += 8)
            out[(size_t)(n0 + ty + i) * 1024 + k0 + tx] = __float2half_rn(t[tx][ty + i]);
    }
}

// ---------------- residual + LayerNorm ---------------------------------------
template <bool DUAL>
__global__ __launch_bounds__(256) void add_ln_kernel(
    const float* __restrict__ A, const float* __restrict__ Bb,
    const float* __restrict__ g, const float* __restrict__ be,
    float* __restrict__ out, __half* __restrict__ outh)
{
    const int row = blockIdx.x;
    const int tid = threadIdx.x;

    const float4 a = ((const float4*)(A + (size_t)row * D_MODEL))[tid];
    const float4 b = ((const float4*)(Bb + (size_t)row * D_MODEL))[tid];
    float4 v = make_float4(a.x + b.x, a.y + b.y, a.z + b.z, a.w + b.w);

    float sum = v.x + v.y + v.z + v.w;
    float sq = v.x * v.x + v.y * v.y + v.z * v.z + v.w * v.w;
#pragma unroll
    for (int off = 16; off > 0; off >>= 1) {
        sum += __shfl_xor_sync(0xFFFFFFFF, sum, off);
        sq  += __shfl_xor_sync(0xFFFFFFFF, sq, off);
    }
    __shared__ float ssum[8], ssq[8];
    __shared__ float s_mu, s_inv;
    const int wid = tid >> 5, lane = tid & 31;
    if (lane == 0) { ssum[wid] = sum; ssq[wid] = sq; }
    __syncthreads();
    if (tid == 0) {
        float ts = 0.f, tq2 = 0.f;
#pragma unroll
        for (int i = 0; i < 8; i++) { ts += ssum[i]; tq2 += ssq[i]; }
        const float mu = ts * (1.f / D_MODEL);
        const float var = tq2 * (1.f / D_MODEL) - mu * mu;
        s_mu = mu;
        s_inv = rsqrtf(var + EPS);
    }
    __syncthreads();
    const float mu = s_mu, inv = s_inv;

    const float4 gv = ((const float4*)g)[tid];
    const float4 bev = ((const float4*)be)[tid];
    float4 r;
    r.x = (v.x - mu) * inv * gv.x + bev.x;
    r.y = (v.y - mu) * inv * gv.y + bev.y;
    r.z = (v.z - mu) * inv * gv.z + bev.z;
    r.w = (v.w - mu) * inv * gv.w + bev.w;
    ((float4*)(out + (size_t)row * D_MODEL))[tid] = r;
    if (DUAL) {
        __half2* op = (__half2*)(outh + (size_t)row * D_MODEL);
        op[2 * tid]     = __floats2half2_rn(r.x, r.y);
        op[2 * tid + 1] = __floats2half2_rn(r.z, r.w);
    }
}

// ---------------- launch ------------------------------------------------------
extern "C" void kernel_launch(void* const* d_in, const int* in_sizes, int n_in,
                              void* d_out, int out_size)
{
    const float* x   = (const float*)d_in[0];
    const float* Wq  = (const float*)d_in[1];
    const float* bq  = (const float*)d_in[2];
    const float* Wk  = (const float*)d_in[3];
    const float* bk  = (const float*)d_in[4];
    const float* Wv  = (const float*)d_in[5];
    const float* bv  = (const float*)d_in[6];
    const float* Wo  = (const float*)d_in[7];
    const float* bo  = (const float*)d_in[8];
    const float* g1  = (const float*)d_in[9];
    const float* be1 = (const float*)d_in[10];
    const float* W1  = (const float*)d_in[11];
    const float* b1  = (const float*)d_in[12];
    const float* W2  = (const float*)d_in[13];
    const float* b2  = (const float*)d_in[14];
    const float* g2  = (const float*)d_in[15];
    const float* be2 = (const float*)d_in[16];
    float* out = (float*)d_out;

    __half *xh, *qkv, *vt, *Bqkv, *Bo, *B1, *B2, *ctx, *y1h, *hh;
    float *bqkv, *tmp, *y1;
    cudaGetSymbolAddress((void**)&xh,   g_xh);
    cudaGetSymbolAddress((void**)&qkv,  g_qkv);
    cudaGetSymbolAddress((void**)&vt,   g_vt);
    cudaGetSymbolAddress((void**)&Bqkv, g_Bqkv);
    cudaGetSymbolAddress((void**)&Bo,   g_Bo);
    cudaGetSymbolAddress((void**)&B1,   g_B1);
    cudaGetSymbolAddress((void**)&B2,   g_B2);
    cudaGetSymbolAddress((void**)&ctx,  g_ctx);
    cudaGetSymbolAddress((void**)&y1h,  g_y1h);
    cudaGetSymbolAddress((void**)&hh,   g_hh);
    cudaGetSymbolAddress((void**)&bqkv, g_bqkv);
    cudaGetSymbolAddress((void**)&tmp,  g_tmp);
    cudaGetSymbolAddress((void**)&y1,   g_y1);

    cudaFuncSetAttribute(gemm_h<0, 0, 0>, cudaFuncAttributeMaxDynamicSharedMemorySize, GSMEM_TOTAL);
    cudaFuncSetAttribute(gemm_h<0, 1, 1>, cudaFuncAttributeMaxDynamicSharedMemorySize, GSMEM_TOTAL);
    cudaFuncSetAttribute(gemm_h<1, 1, 0>, cudaFuncAttributeMaxDynamicSharedMemorySize, GSMEM_TOTAL);

    // 1-3: prep
    prep_x<<<ROWS, 256>>>(x, xh);
    pack_bias<<<3, 1024>>>(bq, bk, bv, bqkv);
    prep_weights<<<dim3(32, 32, 6), dim3(32, 8)>>>(Wq, Wk, Wv, Wo, W1, W2,
                                                   Bqkv, Bo, B1, B2);
    // 4: fused QKV (Q,K fp16 to qkv; V transposed to vt)
    gemm_h<0, 1, 1><<<dim3(QKVN / 256, ROWS / 128), 512, GSMEM_TOTAL>>>(
        xh, Bqkv, bqkv, nullptr, qkv, vt, QKVN);
    // 5: tensor-core attention
    attn_mma<<<dim3(SEQ / 64, BH), 128>>>(qkv, vt, ctx);
    // 6: Wo (fp32 out)   <-- ncu captures this launch
    gemm_h<0, 0, 0><<<dim3(D_MODEL / 256, ROWS / 128), 512, GSMEM_TOTAL>>>(
        ctx, Bo, bo, tmp, nullptr, nullptr, D_MODEL);
    // 7: LN1
    add_ln_kernel<true><<<ROWS, 256>>>(x, tmp, g1, be1, y1, y1h);
    // 8: W1 + ReLU (fp16 out)
    gemm_h<1, 1, 0><<<dim3(D_MODEL / 256, ROWS / 128), 512, GSMEM_TOTAL>>>(
        y1h, B1, b1, nullptr, hh, nullptr, D_MODEL);
    // 9: W2 (fp32 out)
    gemm_h<0, 0, 0><<<dim3(D_MODEL / 256, ROWS / 128), 512, GSMEM_TOTAL>>>(
        hh, B2, b2, tmp, nullptr, nullptr, D_MODEL);
    // 10: LN2 -> output
    add_ln_kernel<false><<<ROWS, 256>>>(y1, tmp, g2, be2, out, nullptr);
}

// round 10
// speedup vs baseline: 1.1561x; 1.0014x over previous
#include <cuda_runtime.h>
#include <cuda_fp16.h>
#include <cstdint>

#define D_MODEL 1024
#define N_HEADS 16
#define D_HEAD  64
#define BATCH   4
#define SEQ     1024
#define ROWS    (BATCH * SEQ)        // 4096
#define BH      (BATCH * N_HEADS)    // 64
#define QKVN    3072
#define GK      1024
#define EPS     1e-5f

// ---------------- scratch ----------------------------------------------------
__device__ __align__(16) __half g_xh  [ROWS * D_MODEL];
__device__ __align__(16) __half g_qkv [ROWS * QKVN];
__device__ __align__(16) __half g_vt  [BH * D_HEAD * SEQ];   // V transposed [bh][d][s]
__device__ __align__(16) __half g_Bqkv[QKVN * D_MODEL];
__device__ __align__(16) __half g_Bo  [D_MODEL * D_MODEL];
__device__ __align__(16) __half g_B1  [D_MODEL * D_MODEL];
__device__ __align__(16) __half g_B2  [D_MODEL * D_MODEL];
__device__ __align__(16) __half g_ctx [ROWS * D_MODEL];
__device__ __align__(16) __half g_y1h [ROWS * D_MODEL];
__device__ __align__(16) __half g_hh  [ROWS * D_MODEL];
__device__ __align__(16) float  g_bqkv[QKVN];
__device__ __align__(16) float  g_tmp [ROWS * D_MODEL];
__device__ __align__(16) float  g_y1  [ROWS * D_MODEL];

// ---------------- helpers ----------------------------------------------------
__device__ __forceinline__ uint32_t smem_u32(const void* p) {
    uint32_t a;
    asm("{ .reg .u64 t; cvta.to.shared.u64 t, %1; cvt.u32.u64 %0, t; }" : "=r"(a) : "l"(p));
    return a;
}
#define SWZ(o) ((o) ^ (((o) >> 3) & 0x70))

__device__ __forceinline__ void cp16(uint32_t dst, const void* src) {
    asm volatile("cp.async.cg.shared.global [%0], [%1], 16;" :: "r"(dst), "l"(src) : "memory");
}
__device__ __forceinline__ void cp_commit() {
    asm volatile("cp.async.commit_group;" ::: "memory");
}

__device__ __forceinline__ void ldsm4(uint32_t& r0, uint32_t& r1, uint32_t& r2, uint32_t& r3,
                                      uint32_t a) {
    asm volatile("ldmatrix.sync.aligned.m8n8.x4.shared.b16 {%0,%1,%2,%3}, [%4];"
                 : "=r"(r0), "=r"(r1), "=r"(r2), "=r"(r3) : "r"(a));
}
__device__ __forceinline__ void mma_h(float* c, const uint32_t* a, uint32_t b0, uint32_t b1) {
    asm volatile(
        "mma.sync.aligned.m16n8k16.row.col.f32.f16.f16.f32 "
        "{%0,%1,%2,%3}, {%4,%5,%6,%7}, {%8,%9}, {%0,%1,%2,%3};"
        : "+f"(c[0]), "+f"(c[1]), "+f"(c[2]), "+f"(c[3])
        : "r"(a[0]), "r"(a[1]), "r"(a[2]), "r"(a[3]), "r"(b0), "r"(b1));
}

// ---------------- fp16 GEMM: C[m][n] = A[m][k] * Bt[n][k]^T + bias -----------
// tile 128x256x128, 512 threads (16 warps: 4m x 4n), 2-stage cp.async.
// Stage layout: A sub0 [0,16K), A sub1 [16K,32K), B sub0 [32K,64K), B sub1 [64K,96K)
// (sub0 = k 0..63 of the chunk, sub1 = k 64..127; each sub keeps 128B rows so
// the proven SWZ/ldsm addressing is reused unchanged.)
#define STAGE_BYTES 98304
#define GSMEM_TOTAL (2 * STAGE_BYTES)         // 196608
#define A_SUB 16384u
#define B_OFF 32768u
#define B_SUB 32768u

template <int RELU, int OUTHALF, int VT>
__global__ void __launch_bounds__(512, 1) gemm_h(
    const __half* __restrict__ A, const __half* __restrict__ Bt,
    const float* __restrict__ bias, float* __restrict__ Cf,
    __half* __restrict__ Ch, __half* __restrict__ vt, int Nld)
{
    extern __shared__ char sm[];
    const uint32_t sb = smem_u32(sm);
    const int tid = threadIdx.x, wid = tid >> 5, lane = tid & 31;
    const int m0 = blockIdx.y * 128, n0 = blockIdx.x * 256;
    const int wM = (wid & 3) * 32, wN = (wid >> 2) * 64;

    float acc[2][8][4];
#pragma unroll
    for (int t = 0; t < 2; t++)
#pragma unroll
        for (int n = 0; n < 8; n++)
#pragma unroll
            for (int j = 0; j < 4; j++) acc[t][n][j] = 0.f;

    // load one 128-k stage (two 64-k sub-tiles)
    auto load_stage = [&](int s, int k0) {
        const uint32_t base = sb + (uint32_t)s * STAGE_BYTES;
#pragma unroll
        for (int s2 = 0; s2 < 2; s2++) {
            const int kk = k0 + s2 * 64;
#pragma unroll
            for (int i = 0; i < 2; i++) {       // A: 1024 chunks per sub
                int c = tid + i * 512;
                int r = c >> 3, q = c & 7;
                cp16(base + s2 * A_SUB + SWZ((uint32_t)(r * 128 + q * 16)),
                     A + (size_t)(m0 + r) * GK + kk + q * 8);
            }
#pragma unroll
            for (int i = 0; i < 4; i++) {       // B: 2048 chunks per sub
                int c = tid + i * 512;
                int r = c >> 3, q = c & 7;
                cp16(base + B_OFF + s2 * B_SUB + SWZ((uint32_t)(r * 128 + q * 16)),
                     Bt + (size_t)(n0 + r) * GK + kk + q * 8);
            }
        }
    };

    load_stage(0, 0); cp_commit();

    const int lr15 = lane & 15, l16 = (lane & 16) ? 16 : 0;
    const int bR = (lane & 7) + ((lane & 16) ? 8 : 0), b16 = (lane & 8) ? 16 : 0;

    for (int it = 0; it < 8; it++) {
        if (it + 1 < 8) { load_stage((it + 1) & 1, (it + 1) * 128); cp_commit(); }
        if (it + 1 < 8) asm volatile("cp.async.wait_group 1;" ::: "memory");
        else            asm volatile("cp.async.wait_group 0;" ::: "memory");
        __syncthreads();

        const uint32_t stB = sb + (uint32_t)(it & 1) * STAGE_BYTES;
#pragma unroll
        for (int kb = 0; kb < 8; kb++) {
            const uint32_t aB = stB + (kb >= 4 ? A_SUB : 0u);
            const uint32_t bB = stB + B_OFF + (kb >= 4 ? B_SUB : 0u);
            const int kq = (kb & 3) * 32;
            uint32_t a[2][4];
#pragma unroll
            for (int t = 0; t < 2; t++)
                ldsm4(a[t][0], a[t][1], a[t][2], a[t][3],
                      aB + SWZ((uint32_t)((wM + t * 16 + lr15) * 128 + kq + l16)));
#pragma unroll
            for (int nn = 0; nn < 4; nn++) {
                uint32_t b0, b1, b2, b3;
                ldsm4(b0, b1, b2, b3,
                      bB + SWZ((uint32_t)((wN + nn * 16 + bR) * 128 + kq + b16)));
#pragma unroll
                for (int t = 0; t < 2; t++) {
                    mma_h(acc[t][2 * nn],     a[t], b0, b1);
                    mma_h(acc[t][2 * nn + 1], a[t], b2, b3);
                }
            }
        }
        __syncthreads();
    }

    const int tq = lane & 3, g = lane >> 2;
#pragma unroll
    for (int t = 0; t < 2; t++) {
        const int r0 = m0 + wM + t * 16 + g;
#pragma unroll
        for (int n = 0; n < 8; n++) {
            const int cc = n0 + wN + n * 8 + 2 * tq;
            const float2 bv = *(const float2*)(bias + cc);
            float v0 = acc[t][n][0] + bv.x;
            float v1 = acc[t][n][1] + bv.y;
            float v2 = acc[t][n][2] + bv.x;
            float v3 = acc[t][n][3] + bv.y;
            if (RELU) {
                v0 = fmaxf(v0, 0.f); v1 = fmaxf(v1, 0.f);
                v2 = fmaxf(v2, 0.f); v3 = fmaxf(v3, 0.f);
            }
            if (VT && cc >= 2048) {
                const int b = r0 >> 10, s = r0 & 1023;
                const int rel = cc - 2048;
                const int h = rel >> 6, d = rel & 63;
                __half* vp = vt + ((size_t)(b * 16 + h) * 64 + d) * 1024 + s;
                vp[0]        = __float2half_rn(v0);
                vp[1024]     = __float2half_rn(v1);
                vp[8]        = __float2half_rn(v2);
                vp[1024 + 8] = __float2half_rn(v3);
            } else if (OUTHALF) {
                *(__half2*)(Ch + (size_t)r0 * Nld + cc)       = __floats2half2_rn(v0, v1);
                *(__half2*)(Ch + (size_t)(r0 + 8) * Nld + cc) = __floats2half2_rn(v2, v3);
            } else {
                *(float2*)(Cf + (size_t)r0 * Nld + cc)       = make_float2(v0, v1);
                *(float2*)(Cf + (size_t)(r0 + 8) * Nld + cc) = make_float2(v2, v3);
            }
        }
    }
}

// ---------------- tensor-core flash attention (R6-proven, 64-row q-tiles) ----
__global__ void __launch_bounds__(128) attn_mma(const __half* __restrict__ qkv,
                                               const __half* __restrict__ vt,
                                               __half* __restrict__ ctx)
{
    __shared__ __align__(16) __half Qs[64 * 64];
    __shared__ __align__(16) __half Ks[2][64 * 64];
    __shared__ __align__(16) __half Vts[2][64 * 64];

    const int bh = blockIdx.y, b = bh >> 4, h = bh & 15;
    const int s0 = blockIdx.x * 64;
    const int tid = threadIdx.x, wid = tid >> 5, lane = tid & 31;
    const uint32_t qB = smem_u32(Qs);
    const uint32_t kB0 = smem_u32(Ks), vB0 = smem_u32(Vts);

#pragma unroll
    for (int i = 0; i < 4; i++) {
        int c = tid + i * 128;
        int r = c >> 3, q = c & 7;
        cp16(qB + SWZ((uint32_t)(r * 128 + q * 16)),
             qkv + (size_t)(b * SEQ + s0 + r) * QKVN + h * 64 + q * 8);
    }
    auto load_kv = [&](int buf, int t) {
#pragma unroll
        for (int i = 0; i < 4; i++) {
            int c = tid + i * 128;
            int r = c >> 3, q = c & 7;
            cp16(kB0 + buf * 8192u + SWZ((uint32_t)(r * 128 + q * 16)),
                 qkv + (size_t)(b * SEQ + t * 64 + r) * QKVN + 1024 + h * 64 + q * 8);
            cp16(vB0 + buf * 8192u + SWZ((uint32_t)(r * 128 + q * 16)),
                 vt + ((size_t)bh * 64 + r) * SEQ + t * 64 + q * 8);
        }
    };
    load_kv(0, 0); cp_commit();
    load_kv(1, 1); cp_commit();
    asm volatile("cp.async.wait_group 1;" ::: "memory");
    __syncthreads();

    const int lr15 = lane & 15, l16 = (lane & 16) ? 16 : 0;
    const int bR = (lane & 7) + ((lane & 16) ? 8 : 0), b16 = (lane & 8) ? 16 : 0;

    uint32_t aq[4][4];
    const __half2 sc = __floats2half2_rn(0.125f, 0.125f);
#pragma unroll
    for (int kb = 0; kb < 4; kb++) {
        ldsm4(aq[kb][0], aq[kb][1], aq[kb][2], aq[kb][3],
              qB + SWZ((uint32_t)((wid * 16 + lr15) * 128 + kb * 32 + l16)));
#pragma unroll
        for (int j = 0; j < 4; j++) {
            __half2 v = *reinterpret_cast<__half2*>(&aq[kb][j]);
            v = __hmul2(v, sc);
            aq[kb][j] = *reinterpret_cast<uint32_t*>(&v);
        }
    }

    float o[8][4];
#pragma unroll
    for (int j = 0; j < 8; j++)
#pragma unroll
        for (int k = 0; k < 4; k++) o[j][k] = 0.f;
    float mr0 = -1e30f, mr1 = -1e30f, lp0 = 0.f, lp1 = 0.f;

    for (int t = 0; t < 16; t++) {
        const uint32_t kB = kB0 + (t & 1) * 8192u;
        const uint32_t vB = vB0 + (t & 1) * 8192u;

        float s[8][4];
#pragma unroll
        for (int j = 0; j < 8; j++)
#pragma unroll
            for (int k = 0; k < 4; k++) s[j][k] = 0.f;
#pragma unroll
        for (int kb = 0; kb < 4; kb++) {
#pragma unroll
            for (int nn = 0; nn < 4; nn++) {
                uint32_t b0, b1, b2, b3;
                ldsm4(b0, b1, b2, b3,
                      kB + SWZ((uint32_t)((nn * 16 + bR) * 128 + kb * 32 + b16)));
                mma_h(s[2 * nn],     aq[kb], b0, b1);
                mma_h(s[2 * nn + 1], aq[kb], b2, b3);
            }
        }

        float mt0 = s[0][0], mt1 = s[0][2];
#pragma unroll
        for (int j = 0; j < 8; j++) {
            mt0 = fmaxf(mt0, fmaxf(s[j][0], s[j][1]));
            mt1 = fmaxf(mt1, fmaxf(s[j][2], s[j][3]));
        }
#pragma unroll
        for (int off = 1; off <= 2; off <<= 1) {
            mt0 = fmaxf(mt0, __shfl_xor_sync(0xFFFFFFFF, mt0, off));
            mt1 = fmaxf(mt1, __shfl_xor_sync(0xFFFFFFFF, mt1, off));
        }
        const float nm0 = fmaxf(mr0, mt0), nm1 = fmaxf(mr1, mt1);
        const float al0 = __expf(mr0 - nm0), al1 = __expf(mr1 - nm1);
        mr0 = nm0; mr1 = nm1;
        float ps0 = 0.f, ps1 = 0.f;
#pragma unroll
        for (int j = 0; j < 8; j++) {
            s[j][0] = __expf(s[j][0] - nm0);
            s[j][1] = __expf(s[j][1] - nm0);
            s[j][2] = __expf(s[j][2] - nm1);
            s[j][3] = __expf(s[j][3] - nm1);
            ps0 += s[j][0] + s[j][1];
            ps1 += s[j][2] + s[j][3];
        }
        lp0 = lp0 * al0 + ps0;
        lp1 = lp1 * al1 + ps1;
#pragma unroll
        for (int j = 0; j < 8; j++) {
            o[j][0] *= al0; o[j][1] *= al0;
            o[j][2] *= al1; o[j][3] *= al1;
        }

#pragma unroll
        for (int kb = 0; kb < 4; kb++) {
            uint32_t pa[4];
            __half2 p0 = __floats2half2_rn(s[2 * kb][0], s[2 * kb][1]);
            __half2 p1 = __floats2half2_rn(s[2 * kb][2], s[2 * kb][3]);
            __half2 p2 = __floats2half2_rn(s[2 * kb + 1][0], s[2 * kb + 1][1]);
            __half2 p3 = __floats2half2_rn(s[2 * kb + 1][2], s[2 * kb + 1][3]);
            pa[0] = *reinterpret_cast<uint32_t*>(&p0);
            pa[1] = *reinterpret_cast<uint32_t*>(&p1);
            pa[2] = *reinterpret_cast<uint32_t*>(&p2);
            pa[3] = *reinterpret_cast<uint32_t*>(&p3);
#pragma unroll
            for (int nn = 0; nn < 4; nn++) {
                uint32_t b0, b1, b2, b3;
                ldsm4(b0, b1, b2, b3,
                      vB + SWZ((uint32_t)((nn * 16 + bR) * 128 + kb * 32 + b16)));
                mma_h(o[2 * nn],     pa, b0, b1);
                mma_h(o[2 * nn + 1], pa, b2, b3);
            }
        }

        __syncthreads();
        if (t + 2 < 16) load_kv(t & 1, t + 2);
        cp_commit();
        asm volatile("cp.async.wait_group 1;" ::: "memory");
        __syncthreads();
    }

#pragma unroll
    for (int off = 1; off <= 2; off <<= 1) {
        lp0 += __shfl_xor_sync(0xFFFFFFFF, lp0, off);
        lp1 += __shfl_xor_sync(0xFFFFFFFF, lp1, off);
    }
    const float i0 = 1.f / lp0, i1 = 1.f / lp1;
    const int g = lane >> 2, tq = lane & 3;
    const int r0 = b * SEQ + s0 + wid * 16 + g;
#pragma unroll
    for (int j = 0; j < 8; j++) {
        const int cc = h * 64 + 8 * j + 2 * tq;
        *(__half2*)(ctx + (size_t)r0 * D_MODEL + cc) =
            __floats2half2_rn(o[j][0] * i0, o[j][1] * i0);
        *(__half2*)(ctx + (size_t)(r0 + 8) * D_MODEL + cc) =
            __floats2half2_rn(o[j][2] * i1, o[j][3] * i1);
    }
}

// ---------------- fused prep (R5-proven) --------------------------------------
__global__ void prep_kernel(
    const float* __restrict__ x,
    const float* __restrict__ Wq, const float* __restrict__ Wk, const float* __restrict__ Wv,
    const float* __restrict__ Wo, const float* __restrict__ W1, const float* __restrict__ W2,
    const float* __restrict__ bq, const float* __restrict__ bk, const float* __restrict__ bv,
    __half* __restrict__ xh, __half* __restrict__ Bqkv,
    __half* __restrict__ Bo, __half* __restrict__ B1, __half* __restrict__ B2,
    float* __restrict__ bqkv)
{
    const int z = blockIdx.z;
    const int tx = threadIdx.x, ty = threadIdx.y;
    const int tid = ty * 32 + tx;

    if (z == 0) {
        const int c0 = blockIdx.x * 32, r0 = blockIdx.y * 32;
#pragma unroll
        for (int i = 0; i < 32; i += 8)
            xh[(size_t)(r0 + ty + i) * 1024 + c0 + tx] =
                __float2half_rn(x[(size_t)(r0 + ty + i) * 1024 + c0 + tx]);
        if (blockIdx.x == 0 && blockIdx.y == 0) {
            for (int i = tid; i < 3072; i += 256)
                bqkv[i] = (i < 1024) ? bq[i] : (i < 2048) ? bk[i - 1024] : bv[i - 2048];
        }
        return;
    }
    if (blockIdx.y >= 32) return;
    __shared__ float t[32][33];

    if (z <= 3) {
        const float* W = (z == 1) ? Wq : (z == 2) ? Wk : Wv;
        __half* out = Bqkv + (size_t)(z - 1) * 1024 * 1024;
        const int hh = blockIdx.x >> 1, d0 = (blockIdx.x & 1) * 32;
        const int k0 = blockIdx.y * 32;
#pragma unroll
        for (int i = 0; i < 32; i += 8)
            t[ty + i][tx] = W[((size_t)hh * 1024 + k0 + ty + i) * 64 + d0 + tx];
        __syncthreads();
#pragma unroll
        for (int i = 0; i < 32; i += 8)
            out[(size_t)(hh * 64 + d0 + ty + i) * 1024 + k0 + tx] =
                __float2half_rn(t[tx][ty + i]);
    } else {
        const float* W = (z == 4) ? Wo : (z == 5) ? W1 : W2;
        __half* out = (z == 4) ? Bo : (z == 5) ? B1 : B2;
        const int n0 = blockIdx.x * 32, k0 = blockIdx.y * 32;
#pragma unroll
        for (int i = 0; i < 32; i += 8)
            t[ty + i][tx] = W[(size_t)(k0 + ty + i) * 1024 + n0 + tx];
        __syncthreads();
#pragma unroll
        for (int i = 0; i < 32; i += 8)
            out[(size_t)(n0 + ty + i) * 1024 + k0 + tx] = __float2half_rn(t[tx][ty + i]);
    }
}

// ---------------- residual + LayerNorm ---------------------------------------
template <bool DUAL>
__global__ __launch_bounds__(256) void add_ln_kernel(
    const float* __restrict__ A, const float* __restrict__ Bb,
    const float* __restrict__ g, const float* __restrict__ be,
    float* __restrict__ out, __half* __restrict__ outh)
{
    const int row = blockIdx.x;
    const int tid = threadIdx.x;

    const float4 a = ((const float4*)(A + (size_t)row * D_MODEL))[tid];
    const float4 b = ((const float4*)(Bb + (size_t)row * D_MODEL))[tid];
    float4 v = make_float4(a.x + b.x, a.y + b.y, a.z + b.z, a.w + b.w);

    float sum = v.x + v.y + v.z + v.w;
    float sq = v.x * v.x + v.y * v.y + v.z * v.z + v.w * v.w;
#pragma unroll
    for (int off = 16; off > 0; off >>= 1) {
        sum += __shfl_xor_sync(0xFFFFFFFF, sum, off);
        sq  += __shfl_xor_sync(0xFFFFFFFF, sq, off);
    }
    __shared__ float ssum[8], ssq[8];
    __shared__ float s_mu, s_inv;
    const int wid = tid >> 5, lane = tid & 31;
    if (lane == 0) { ssum[wid] = sum; ssq[wid] = sq; }
    __syncthreads();
    if (tid == 0) {
        float ts = 0.f, tq2 = 0.f;
#pragma unroll
        for (int i = 0; i < 8; i++) { ts += ssum[i]; tq2 += ssq[i]; }
        const float mu = ts * (1.f / D_MODEL);
        const float var = tq2 * (1.f / D_MODEL) - mu * mu;
        s_mu = mu;
        s_inv = rsqrtf(var + EPS);
    }
    __syncthreads();
    const float mu = s_mu, inv = s_inv;

    const float4 gv = ((const float4*)g)[tid];
    const float4 bev = ((const float4*)be)[tid];
    float4 r;
    r.x = (v.x - mu) * inv * gv.x + bev.x;
    r.y = (v.y - mu) * inv * gv.y + bev.y;
    r.z = (v.z - mu) * inv * gv.z + bev.z;
    r.w = (v.w - mu) * inv * gv.w + bev.w;
    ((float4*)(out + (size_t)row * D_MODEL))[tid] = r;
    if (DUAL) {
        __half2* op = (__half2*)(outh + (size_t)row * D_MODEL);
        op[2 * tid]     = __floats2half2_rn(r.x, r.y);
        op[2 * tid + 1] = __floats2half2_rn(r.z, r.w);
    }
}

// ---------------- launch ------------------------------------------------------
extern "C" void kernel_launch(void* const* d_in, const int* in_sizes, int n_in,
                              void* d_out, int out_size)
{
    const float* x   = (const float*)d_in[0];
    const float* Wq  = (const float*)d_in[1];
    const float* bq  = (const float*)d_in[2];
    const float* Wk  = (const float*)d_in[3];
    const float* bk  = (const float*)d_in[4];
    const float* Wv  = (const float*)d_in[5];
    const float* bv  = (const float*)d_in[6];
    const float* Wo  = (const float*)d_in[7];
    const float* bo  = (const float*)d_in[8];
    const float* g1  = (const float*)d_in[9];
    const float* be1 = (const float*)d_in[10];
    const float* W1  = (const float*)d_in[11];
    const float* b1  = (const float*)d_in[12];
    const float* W2  = (const float*)d_in[13];
    const float* b2  = (const float*)d_in[14];
    const float* g2  = (const float*)d_in[15];
    const float* be2 = (const float*)d_in[16];
    float* out = (float*)d_out;

    __half *xh, *qkv, *vt, *Bqkv, *Bo, *B1, *B2, *ctx, *y1h, *hh;
    float *bqkv, *tmp, *y1;
    cudaGetSymbolAddress((void**)&xh,   g_xh);
    cudaGetSymbolAddress((void**)&qkv,  g_qkv);
    cudaGetSymbolAddress((void**)&vt,   g_vt);
    cudaGetSymbolAddress((void**)&Bqkv, g_Bqkv);
    cudaGetSymbolAddress((void**)&Bo,   g_Bo);
    cudaGetSymbolAddress((void**)&B1,   g_B1);
    cudaGetSymbolAddress((void**)&B2,   g_B2);
    cudaGetSymbolAddress((void**)&ctx,  g_ctx);
    cudaGetSymbolAddress((void**)&y1h,  g_y1h);
    cudaGetSymbolAddress((void**)&hh,   g_hh);
    cudaGetSymbolAddress((void**)&bqkv, g_bqkv);
    cudaGetSymbolAddress((void**)&tmp,  g_tmp);
    cudaGetSymbolAddress((void**)&y1,   g_y1);

    cudaFuncSetAttribute(gemm_h<0, 0, 0>, cudaFuncAttributeMaxDynamicSharedMemorySize, GSMEM_TOTAL);
    cudaFuncSetAttribute(gemm_h<0, 1, 1>, cudaFuncAttributeMaxDynamicSharedMemorySize, GSMEM_TOTAL);
    cudaFuncSetAttribute(gemm_h<1, 1, 0>, cudaFuncAttributeMaxDynamicSharedMemorySize, GSMEM_TOTAL);

    // 1: fused prep
    prep_kernel<<<dim3(32, 128, 7), dim3(32, 8)>>>(x, Wq, Wk, Wv, Wo, W1, W2,
                                                   bq, bk, bv,
                                                   xh, Bqkv, Bo, B1, B2, bqkv);
    // 2: fused QKV (Q,K fp16 to qkv; V transposed to vt)
    gemm_h<0, 1, 1><<<dim3(QKVN / 256, ROWS / 128), 512, GSMEM_TOTAL>>>(
        xh, Bqkv, bqkv, nullptr, qkv, vt, QKVN);
    // 3: tensor-core attention
    attn_mma<<<dim3(SEQ / 64, BH), 128>>>(qkv, vt, ctx);
    // 4: Wo (fp32 out)
    gemm_h<0, 0, 0><<<dim3(D_MODEL / 256, ROWS / 128), 512, GSMEM_TOTAL>>>(
        ctx, Bo, bo, tmp, nullptr, nullptr, D_MODEL);
    // 5: LN1
    add_ln_kernel<true><<<ROWS, 256>>>(x, tmp, g1, be1, y1, y1h);
    // 6: W1 + ReLU (fp16 out)  <-- ncu window
    gemm_h<1, 1, 0><<<dim3(D_MODEL / 256, ROWS / 128), 512, GSMEM_TOTAL>>>(
        y1h, B1, b1, nullptr, hh, nullptr, D_MODEL);
    // 7: W2 (fp32 out)
    gemm_h<0, 0, 0><<<dim3(D_MODEL / 256, ROWS / 128), 512, GSMEM_TOTAL>>>(
        hh, B2, b2, tmp, nullptr, nullptr, D_MODEL);
    // 8: LN2 -> output
    add_ln_kernel<false><<<ROWS, 256>>>(y1, tmp, g2, be2, out, nullptr);
}